// round 13
// baseline (speedup 1.0000x reference)
#include <cuda_runtime.h>

#define SS   384
#define SS1  385
#define NH   8
#define NB   32
#define NBH  256          // NB*NH
#define KD   16
#define EPSF 1e-8f
#define GWEPS 0.05f

// ---------------- scratch (static device globals; no allocations) ----------
__device__ float        g_symP[NBH * SS * SS];       // 151 MB
__device__ float        g_deg [NBH * SS];
__device__ unsigned int g_mx  [NBH];
__device__ float        g_a   [NBH * SS];
__device__ float        g_cC1 [NBH * SS];
__device__ float        g_cC2 [NBH * KD];
__device__ float        g_csW [NBH * KD];
__device__ float        g_W   [NBH * SS * KD];
__device__ float        g_tens[NBH * SS * KD];
__device__ float        g_Km  [NBH * SS * KD];
__device__ float        g_alpha[NBH];
__device__ float        g_vh  [NBH * SS1 * 32];

// ---------------------------------------------------------------------------
__global__ void k_zero() {
    int t = blockIdx.x * blockDim.x + threadIdx.x;
    if (t < NBH * SS) g_deg[t] = 0.f;
    if (t < NBH)      g_mx[t]  = 0u;
}

// symmetrize P[1:,1:] -> symP, accumulate rowsums (deg) and global max
// grid: (78 tile-pairs, NBH), block: (32,32)
__global__ void k_sym(const float* __restrict__ P) {
    __shared__ float sA[32][33];
    __shared__ float sB[32][33];
    __shared__ float wm[32];

    int bh = blockIdx.y;
    int p  = blockIdx.x;
    int ti = 0;
    while (p >= 12 - ti) { p -= 12 - ti; ti++; }
    int tj = ti + p;

    int x = threadIdx.x, y = threadIdx.y;
    const float* Pb = P + bh * SS1 * SS1;
    int r0 = ti * 32, c0 = tj * 32;

    sA[y][x] = Pb[(1 + r0 + y) * SS1 + 1 + c0 + x];
    sB[y][x] = Pb[(1 + c0 + y) * SS1 + 1 + r0 + x];
    __syncthreads();

    float* SPb = g_symP + bh * SS * SS;
    float symA = 0.5f * (sA[y][x] + sB[x][y]);
    float symB = 0.5f * (sB[y][x] + sA[x][y]);
    SPb[(r0 + y) * SS + c0 + x] = symA;
    SPb[(c0 + y) * SS + r0 + x] = symB;

    // row sums (deg): A-tile rows always, B-tile rows only if off-diagonal
    float rs = symA;
    #pragma unroll
    for (int off = 16; off; off >>= 1) rs += __shfl_down_sync(0xffffffffu, rs, off);
    if (x == 0) atomicAdd(&g_deg[bh * SS + r0 + y], rs);
    if (ti != tj) {
        float rs2 = symB;
        #pragma unroll
        for (int off = 16; off; off >>= 1) rs2 += __shfl_down_sync(0xffffffffu, rs2, off);
        if (x == 0) atomicAdd(&g_deg[bh * SS + c0 + y], rs2);
    }

    // block max of symA (B-tile values are the same set transposed)
    float m = symA;
    #pragma unroll
    for (int off = 16; off; off >>= 1) m = fmaxf(m, __shfl_down_sync(0xffffffffu, m, off));
    if (x == 0) wm[y] = m;
    __syncthreads();
    if (y == 0) {
        float mm = wm[x];
        #pragma unroll
        for (int off = 16; off; off >>= 1) mm = fmaxf(mm, __shfl_down_sync(0xffffffffu, mm, off));
        if (x == 0) atomicMax(&g_mx[bh], __float_as_uint(mm));
    }
}

// per-bh: a = deg/sum(deg); cC2[l]=sum_k b_k C2[k,l]^2; w0[l]=sum_k b_k C2[l,k];
// W0 = a (x) w0 ; csW0 = w0 * sum(a).   grid: NBH, block: 256
__global__ void k_scalars(const float* __restrict__ DG, const float* __restrict__ bb) {
    __shared__ float red[256];
    __shared__ float sw0[KD];
    int bh = blockIdx.x, t = threadIdx.x;

    float s = 0.f;
    for (int i = t; i < SS; i += 256) s += g_deg[bh * SS + i];
    red[t] = s; __syncthreads();
    for (int off = 128; off; off >>= 1) { if (t < off) red[t] += red[t + off]; __syncthreads(); }
    float sumdeg = red[0];
    float inv = 1.f / fmaxf(sumdeg, EPSF);
    float sa  = sumdeg * inv;          // == 1 unless degenerate

    for (int i = t; i < SS; i += 256) g_a[bh * SS + i] = g_deg[bh * SS + i] * inv;

    if (t < KD) {
        int l = t;
        float c2 = 0.f, w0 = 0.f;
        for (int k = 0; k < KD; k++) {
            float bk  = bb[bh * KD + k];
            float ckl = DG[bh * KD * KD + k * KD + l];
            float clk = DG[bh * KD * KD + l * KD + k];
            c2 += bk * ckl * ckl;
            w0 += bk * clk;
        }
        g_cC2[bh * KD + l] = c2;
        g_csW[bh * KD + l] = w0 * sa;
        sw0[l] = w0;
    }
    __syncthreads();
    for (int idx = t; idx < SS * KD; idx += 256) {
        int i = idx / KD, l = idx % KD;
        g_W[bh * SS * KD + idx] = g_a[bh * SS + i] * sw0[l];
    }
}

// cC1[i] = 1 - 2*r1/mx + r2/mx^2,  r1=sum symP*a, r2=sum symP^2*a
// grid: (6, NBH), block: 256 (8 warps x 8 rows)
__global__ void k_cc1() {
    __shared__ float sa[SS];
    int bh = blockIdx.y, tile = blockIdx.x, t = threadIdx.x;
    for (int i = t; i < SS; i += 256) sa[i] = g_a[bh * SS + i];
    __syncthreads();
    float invm = 1.f / fmaxf(__uint_as_float(g_mx[bh]), EPSF);
    int w = t / 32, lane = t % 32;
    const float* SPb = g_symP + bh * SS * SS;
    for (int rr = 0; rr < 8; rr++) {
        int row = tile * 64 + w * 8 + rr;
        const float* Pr = SPb + row * SS;
        float r1 = 0.f, r2 = 0.f;
        for (int s = lane; s < SS; s += 32) {
            float p = Pr[s], av = sa[s];
            r1 += p * av;
            r2 += p * p * av;
        }
        #pragma unroll
        for (int off = 16; off; off >>= 1) {
            r1 += __shfl_down_sync(0xffffffffu, r1, off);
            r2 += __shfl_down_sync(0xffffffffu, r2, off);
        }
        if (lane == 0)
            g_cC1[bh * SS + row] = 1.f - 2.f * r1 * invm + r2 * invm * invm;
    }
}

// tens = cC1[i] + cC2[l] - 2*(csW[l] - (symP@W)[i,l]/mx); Km = exp(-tens/eps)
// grid: (6, NBH), block: (16,16)
__global__ void k_tens() {
    __shared__ float sW[SS * KD];     // 24 KB
    __shared__ float sP[64 * 65];     // 16.6 KB
    int bh = blockIdx.y, tile = blockIdx.x;
    int l = threadIdx.x, iy = threadIdx.y;
    int t = iy * 16 + l;

    for (int idx = t; idx < SS * KD; idx += 256) sW[idx] = g_W[bh * SS * KD + idx];

    float acc0 = 0.f, acc1 = 0.f, acc2 = 0.f, acc3 = 0.f;
    int i0 = tile * 64;
    const float* SPb = g_symP + bh * SS * SS;

    for (int s0 = 0; s0 < SS; s0 += 64) {
        __syncthreads();
        for (int idx = t; idx < 64 * 64; idx += 256) {
            int r = idx >> 6, ss = idx & 63;
            sP[r * 65 + ss] = SPb[(i0 + r) * SS + s0 + ss];
        }
        __syncthreads();
        #pragma unroll 4
        for (int ss = 0; ss < 64; ss++) {
            float wv = sW[(s0 + ss) * KD + l];
            acc0 += sP[(iy     ) * 65 + ss] * wv;
            acc1 += sP[(iy + 16) * 65 + ss] * wv;
            acc2 += sP[(iy + 32) * 65 + ss] * wv;
            acc3 += sP[(iy + 48) * 65 + ss] * wv;
        }
    }
    float invm = 1.f / fmaxf(__uint_as_float(g_mx[bh]), EPSF);
    float cc2  = g_cC2[bh * KD + l];
    float cs   = g_csW[bh * KD + l];
    const float inve = 1.f / GWEPS;
    float accs[4] = {acc0, acc1, acc2, acc3};
    #pragma unroll
    for (int r4 = 0; r4 < 4; r4++) {
        int i = i0 + iy + 16 * r4;
        float tens = g_cC1[bh * SS + i] + cc2 - 2.f * (cs - accs[r4] * invm);
        int oi = (bh * SS + i) * KD + l;
        g_tens[oi] = tens;
        g_Km[oi]   = __expf(-tens * inve);
    }
}

// sinkhorn (20 iters) entirely in smem; emits W=T*C2^T (+colsum) or alpha on last
// grid: NBH, block: 384
__global__ void k_sink(const float* __restrict__ DG, const float* __restrict__ bglob, int last) {
    __shared__ float sK[SS * 17];     // 26.1 KB, stride-17 pad
    __shared__ float sv[KD];
    __shared__ float sb[KD];
    __shared__ float sC2[KD * KD];
    __shared__ float wpart[12 * KD];
    __shared__ float wsum[12];

    int bh = blockIdx.x, i = threadIdx.x;
    int w = i / 32, lane = i % 32;

    const float4* Kb = reinterpret_cast<const float4*>(g_Km + bh * SS * KD);
    #pragma unroll
    for (int q = 0; q < 4; q++) {
        float4 v4 = Kb[i * 4 + q];
        sK[i * 17 + 4 * q + 0] = v4.x;
        sK[i * 17 + 4 * q + 1] = v4.y;
        sK[i * 17 + 4 * q + 2] = v4.z;
        sK[i * 17 + 4 * q + 3] = v4.w;
    }
    if (i < KD)       { sv[i] = 1.f; sb[i] = bglob[bh * KD + i]; }
    if (i < KD * KD)  sC2[i] = DG[bh * KD * KD + i];
    float a_i = g_a[bh * SS + i];
    __syncthreads();

    float u = 1.f;
    for (int it = 0; it < 20; it++) {
        float s = 0.f;
        #pragma unroll
        for (int k = 0; k < KD; k++) s += sK[i * 17 + k] * sv[k];
        u = a_i / fmaxf(s, 1e-30f);

        float p[KD];
        #pragma unroll
        for (int k = 0; k < KD; k++) p[k] = sK[i * 17 + k] * u;
        #pragma unroll
        for (int k = 0; k < KD; k++)
            #pragma unroll
            for (int off = 16; off; off >>= 1)
                p[k] += __shfl_down_sync(0xffffffffu, p[k], off);
        if (lane == 0) {
            #pragma unroll
            for (int k = 0; k < KD; k++) wpart[w * KD + k] = p[k];
        }
        __syncthreads();
        if (i < KD) {
            float sm = 0.f;
            #pragma unroll
            for (int ww = 0; ww < 12; ww++) sm += wpart[ww * KD + i];
            sv[i] = sb[i] / fmaxf(sm, 1e-30f);
        }
        __syncthreads();
    }

    float Trow[KD];
    #pragma unroll
    for (int k = 0; k < KD; k++) Trow[k] = u * sK[i * 17 + k] * sv[k];

    if (!last) {
        float Wr[KD];
        #pragma unroll
        for (int l = 0; l < KD; l++) {
            float s = 0.f;
            #pragma unroll
            for (int k = 0; k < KD; k++) s += Trow[k] * sC2[l * KD + k];
            Wr[l] = s;
        }
        float4* Wo = reinterpret_cast<float4*>(g_W + (bh * SS + i) * KD);
        Wo[0] = make_float4(Wr[0],  Wr[1],  Wr[2],  Wr[3]);
        Wo[1] = make_float4(Wr[4],  Wr[5],  Wr[6],  Wr[7]);
        Wo[2] = make_float4(Wr[8],  Wr[9],  Wr[10], Wr[11]);
        Wo[3] = make_float4(Wr[12], Wr[13], Wr[14], Wr[15]);
        // column sums of W -> g_csW
        #pragma unroll
        for (int k = 0; k < KD; k++)
            #pragma unroll
            for (int off = 16; off; off >>= 1)
                Wr[k] += __shfl_down_sync(0xffffffffu, Wr[k], off);
        if (lane == 0) {
            #pragma unroll
            for (int k = 0; k < KD; k++) wpart[w * KD + k] = Wr[k];
        }
        __syncthreads();
        if (i < KD) {
            float sm = 0.f;
            #pragma unroll
            for (int ww = 0; ww < 12; ww++) sm += wpart[ww * KD + i];
            g_csW[bh * KD + i] = sm;
        }
    } else {
        const float* tb = g_tens + (bh * SS + i) * KD;
        float g = 0.f;
        #pragma unroll
        for (int k = 0; k < KD; k++) g += tb[k] * Trow[k];
        #pragma unroll
        for (int off = 16; off; off >>= 1) g += __shfl_down_sync(0xffffffffu, g, off);
        if (lane == 0) wsum[w] = g;
        __syncthreads();
        if (i == 0) {
            float tot = 0.f;
            #pragma unroll
            for (int ww = 0; ww < 12; ww++) tot += wsum[ww];
            g_alpha[bh] = expf(-tot);      // sigma = 1
        }
    }
}

// v projection: vh[b,h,s,d] = sum_k nv[b,s,k]*vw[h*32+d,k] + vb
// grid: (193, 4), block: 256
__global__ void k_vproj(const float* __restrict__ nv, const float* __restrict__ vw,
                        const float* __restrict__ vb) {
    __shared__ float sA [64 * 33];
    __shared__ float sWt[64 * 33];
    int m0 = blockIdx.x * 64, n0 = blockIdx.y * 64;
    int t = threadIdx.x, tx = t % 16, ty = t / 16;
    float acc[4][4] = {};

    for (int k0 = 0; k0 < 256; k0 += 32) {
        __syncthreads();
        for (int idx = t; idx < 64 * 32; idx += 256) {
            int r = idx >> 5, kk = idx & 31;
            int m = m0 + r;
            sA [r * 33 + kk] = (m < NB * SS1) ? nv[m * 256 + k0 + kk] : 0.f;
            sWt[r * 33 + kk] = vw[(n0 + r) * 256 + k0 + kk];
        }
        __syncthreads();
        for (int kk = 0; kk < 32; kk++) {
            float ar[4], bc[4];
            #pragma unroll
            for (int r = 0; r < 4; r++) ar[r] = sA [(ty + 16 * r) * 33 + kk];
            #pragma unroll
            for (int c = 0; c < 4; c++) bc[c] = sWt[(tx + 16 * c) * 33 + kk];
            #pragma unroll
            for (int r = 0; r < 4; r++)
                #pragma unroll
                for (int c = 0; c < 4; c++) acc[r][c] += ar[r] * bc[c];
        }
    }
    #pragma unroll
    for (int r = 0; r < 4; r++) {
        int m = m0 + ty + 16 * r;
        if (m >= NB * SS1) continue;
        int b = m / SS1, s = m % SS1;
        #pragma unroll
        for (int c = 0; c < 4; c++) {
            int n = n0 + tx + 16 * c;
            int h = n >> 5, d = n & 31;
            g_vh[((b * NH + h) * SS1 + s) * 32 + d] = acc[r][c] + vb[n];
        }
    }
}

// attn row 0: [0]=0, [1..384]=1/384
__global__ void k_row0(float* __restrict__ attnOut) {
    int bh = blockIdx.x, t = threadIdx.x;
    float* row = attnOut + bh * SS1 * SS1;
    if (t == 0) row[0] = 0.f;
    float v = 1.f / 384.f;
    for (int j = t; j < SS; j += blockDim.x) row[1 + j] = v;
}

// rows 1..384: Q_hat = max(Q,eps)^(1+alpha), diag zeroed, row-normalized
// grid: (6, NBH), block: 256 (8 warps x 8 rows)
__global__ void k_attn(const float* __restrict__ priorQ, float* __restrict__ attnOut) {
    int bh = blockIdx.y, tile = blockIdx.x, t = threadIdx.x;
    int w = t / 32, lane = t % 32;
    float e = 1.f + g_alpha[bh];
    const float* Qb = priorQ + bh * SS * SS;
    float* Ab = attnOut + bh * SS1 * SS1;

    for (int rr = 0; rr < 8; rr++) {
        int r = tile * 64 + w * 8 + rr;
        const float* qrow = Qb + r * SS;
        float tv[12];
        float sum = 0.f;
        #pragma unroll
        for (int c = 0; c < 12; c++) {
            int m = lane + 32 * c;
            float q = fmaxf(qrow[m], EPSF);
            float x = __powf(q, e);
            if (m == r) x = 0.f;
            tv[c] = x;
            sum += x;
        }
        #pragma unroll
        for (int off = 16; off; off >>= 1) sum += __shfl_xor_sync(0xffffffffu, sum, off);
        float inv = 1.f / fmaxf(sum, EPSF);
        float* arow = Ab + (r + 1) * SS1;
        if (lane == 0) arow[0] = 0.f;
        #pragma unroll
        for (int c = 0; c < 12; c++) arow[1 + lane + 32 * c] = tv[c] * inv;
    }
}

// context: basis[b,i,h,d] = sum_j attn[bh,i,j] * vh[bh,j,d]
// grid: (7, NBH), block: 256 (tx=d 0..31, ty row group)
__global__ void k_ctx(const float* __restrict__ attnOut, float* __restrict__ outBasis) {
    __shared__ float sA[64 * 33];
    __shared__ float sV[32 * 33];
    int bh = blockIdx.y, tile = blockIdx.x, t = threadIdx.x;
    int tx = t % 32, ty = t / 32;
    float acc[8] = {};
    const float* Ab = attnOut + bh * SS1 * SS1;
    const float* Vb = g_vh + bh * SS1 * 32;
    int i0 = tile * 64;

    for (int j0 = 0; j0 < SS1; j0 += 32) {
        __syncthreads();
        for (int idx = t; idx < 64 * 32; idx += 256) {
            int r = idx >> 5, jj = idx & 31;
            int i = i0 + r, j = j0 + jj;
            sA[r * 33 + jj] = (i < SS1 && j < SS1) ? Ab[i * SS1 + j] : 0.f;
        }
        for (int idx = t; idx < 32 * 32; idx += 256) {
            int jj = idx >> 5, d = idx & 31;
            int j = j0 + jj;
            sV[jj * 33 + d] = (j < SS1) ? Vb[j * 32 + d] : 0.f;
        }
        __syncthreads();
        #pragma unroll 4
        for (int jj = 0; jj < 32; jj++) {
            float v = sV[jj * 33 + tx];
            #pragma unroll
            for (int r8 = 0; r8 < 8; r8++) acc[r8] += sA[(ty + 8 * r8) * 33 + jj] * v;
        }
    }
    int b = bh >> 3, h = bh & 7;
    #pragma unroll
    for (int r8 = 0; r8 < 8; r8++) {
        int i = i0 + ty + 8 * r8;
        if (i < SS1)
            outBasis[(b * SS1 + i) * 256 + h * 32 + tx] = acc[r8];
    }
}

// ---------------------------------------------------------------------------
extern "C" void kernel_launch(void* const* d_in, const int* in_sizes, int n_in,
                              void* d_out, int out_size) {
    const float* nv = (const float*)d_in[1];   // name_value_embeddings [32,385,256]
    const float* P  = (const float*)d_in[2];   // shared_attn [32,8,385,385]
    const float* Q  = (const float*)d_in[3];   // prior_Q [32,8,384,384]
    const float* DG = (const float*)d_in[4];   // [32,8,16,16]
    const float* bb = (const float*)d_in[5];   // [32,8,16]
    const float* vw = (const float*)d_in[6];   // [256,256]
    const float* vb = (const float*)d_in[7];   // [256]

    float* outB = (float*)d_out;                                   // basis [32,385,8,32]
    float* outA = (float*)d_out + (out_size - NBH * SS1 * SS1);    // attn  [32,8,385,385]

    k_zero   <<<(NBH * SS + 255) / 256, 256>>>();
    k_sym    <<<dim3(78, NBH), dim3(32, 32)>>>(P);
    k_scalars<<<NBH, 256>>>(DG, bb);
    k_cc1    <<<dim3(6, NBH), 256>>>();
    k_vproj  <<<dim3(193, 4), 256>>>(nv, vw, vb);

    for (int it = 0; it < 5; it++) {
        k_tens<<<dim3(6, NBH), dim3(16, 16)>>>();
        k_sink<<<NBH, 384>>>(DG, bb, it == 4 ? 1 : 0);
    }

    k_row0<<<NBH, 128>>>(outA);
    k_attn<<<dim3(6, NBH), 256>>>(Q, outA);
    k_ctx <<<dim3(7, NBH), 256>>>(outA, outB);
}

// round 14
// speedup vs baseline: 1.0112x; 1.0112x over previous
#include <cuda_runtime.h>

#define SS   384
#define SS1  385
#define NH   8
#define NB   32
#define NBH  256          // NB*NH
#define KD   16
#define EPSF 1e-8f
#define GWEPS 0.05f

// ---------------- scratch (static device globals; no allocations) ----------
__device__ float        g_symP[NBH * SS * SS];       // 151 MB
__device__ float        g_deg [NBH * SS];
__device__ unsigned int g_mx  [NBH];
__device__ float        g_a   [NBH * SS];
__device__ float        g_cC1 [NBH * SS];
__device__ float        g_cC2 [NBH * KD];
__device__ float        g_csW [NBH * KD];
__device__ float        g_W   [NBH * SS * KD];
__device__ float        g_tens[NBH * SS * KD];
__device__ float        g_Km  [NBH * SS * KD];
__device__ float        g_alpha[NBH];
__device__ float        g_vh  [NBH * SS1 * 32];

// ---------------------------------------------------------------------------
__global__ void k_zero() {
    int t = blockIdx.x * blockDim.x + threadIdx.x;
    if (t < NBH * SS) g_deg[t] = 0.f;
    if (t < NBH)      g_mx[t]  = 0u;
}

// symmetrize P[1:,1:] -> symP, accumulate rowsums (deg) and global max
// grid: (78 tile-pairs, NBH), block: (32,32)
__global__ void k_sym(const float* __restrict__ P) {
    __shared__ float sA[32][33];
    __shared__ float sB[32][33];
    __shared__ float wm[32];

    int bh = blockIdx.y;
    int p  = blockIdx.x;
    int ti = 0;
    while (p >= 12 - ti) { p -= 12 - ti; ti++; }
    int tj = ti + p;

    int x = threadIdx.x, y = threadIdx.y;
    const float* Pb = P + bh * SS1 * SS1;
    int r0 = ti * 32, c0 = tj * 32;

    sA[y][x] = Pb[(1 + r0 + y) * SS1 + 1 + c0 + x];
    sB[y][x] = Pb[(1 + c0 + y) * SS1 + 1 + r0 + x];
    __syncthreads();

    float* SPb = g_symP + bh * SS * SS;
    float symA = 0.5f * (sA[y][x] + sB[x][y]);
    float symB = 0.5f * (sB[y][x] + sA[x][y]);
    SPb[(r0 + y) * SS + c0 + x] = symA;
    SPb[(c0 + y) * SS + r0 + x] = symB;

    // row sums (deg): A-tile rows always, B-tile rows only if off-diagonal
    float rs = symA;
    #pragma unroll
    for (int off = 16; off; off >>= 1) rs += __shfl_down_sync(0xffffffffu, rs, off);
    if (x == 0) atomicAdd(&g_deg[bh * SS + r0 + y], rs);
    if (ti != tj) {
        float rs2 = symB;
        #pragma unroll
        for (int off = 16; off; off >>= 1) rs2 += __shfl_down_sync(0xffffffffu, rs2, off);
        if (x == 0) atomicAdd(&g_deg[bh * SS + c0 + y], rs2);
    }

    // block max of symA (B-tile values are the same set transposed)
    float m = symA;
    #pragma unroll
    for (int off = 16; off; off >>= 1) m = fmaxf(m, __shfl_down_sync(0xffffffffu, m, off));
    if (x == 0) wm[y] = m;
    __syncthreads();
    if (y == 0) {
        float mm = wm[x];
        #pragma unroll
        for (int off = 16; off; off >>= 1) mm = fmaxf(mm, __shfl_down_sync(0xffffffffu, mm, off));
        if (x == 0) atomicMax(&g_mx[bh], __float_as_uint(mm));
    }
}

// per-bh: a = deg/sum(deg); cC2[l]=sum_k b_k C2[k,l]^2; w0[l]=sum_k b_k C2[l,k];
// W0 = a (x) w0 ; csW0 = w0 * sum(a).   grid: NBH, block: 256
__global__ void k_scalars(const float* __restrict__ DG, const float* __restrict__ bb) {
    __shared__ float red[256];
    __shared__ float sw0[KD];
    int bh = blockIdx.x, t = threadIdx.x;

    float s = 0.f;
    for (int i = t; i < SS; i += 256) s += g_deg[bh * SS + i];
    red[t] = s; __syncthreads();
    for (int off = 128; off; off >>= 1) { if (t < off) red[t] += red[t + off]; __syncthreads(); }
    float sumdeg = red[0];
    float inv = 1.f / fmaxf(sumdeg, EPSF);
    float sa  = sumdeg * inv;          // == 1 unless degenerate

    for (int i = t; i < SS; i += 256) g_a[bh * SS + i] = g_deg[bh * SS + i] * inv;

    if (t < KD) {
        int l = t;
        float c2 = 0.f, w0 = 0.f;
        for (int k = 0; k < KD; k++) {
            float bk  = bb[bh * KD + k];
            float ckl = DG[bh * KD * KD + k * KD + l];
            float clk = DG[bh * KD * KD + l * KD + k];
            c2 += bk * ckl * ckl;
            w0 += bk * clk;
        }
        g_cC2[bh * KD + l] = c2;
        g_csW[bh * KD + l] = w0 * sa;
        sw0[l] = w0;
    }
    __syncthreads();
    for (int idx = t; idx < SS * KD; idx += 256) {
        int i = idx / KD, l = idx % KD;
        g_W[bh * SS * KD + idx] = g_a[bh * SS + i] * sw0[l];
    }
}

// cC1[i] = 1 - 2*r1/mx + r2/mx^2,  r1=sum symP*a, r2=sum symP^2*a
// grid: (6, NBH), block: 256 (8 warps x 8 rows)
__global__ void k_cc1() {
    __shared__ float sa[SS];
    int bh = blockIdx.y, tile = blockIdx.x, t = threadIdx.x;
    for (int i = t; i < SS; i += 256) sa[i] = g_a[bh * SS + i];
    __syncthreads();
    float invm = 1.f / fmaxf(__uint_as_float(g_mx[bh]), EPSF);
    int w = t / 32, lane = t % 32;
    const float* SPb = g_symP + bh * SS * SS;
    for (int rr = 0; rr < 8; rr++) {
        int row = tile * 64 + w * 8 + rr;
        const float* Pr = SPb + row * SS;
        float r1 = 0.f, r2 = 0.f;
        for (int s = lane; s < SS; s += 32) {
            float p = Pr[s], av = sa[s];
            r1 += p * av;
            r2 += p * p * av;
        }
        #pragma unroll
        for (int off = 16; off; off >>= 1) {
            r1 += __shfl_down_sync(0xffffffffu, r1, off);
            r2 += __shfl_down_sync(0xffffffffu, r2, off);
        }
        if (lane == 0)
            g_cC1[bh * SS + row] = 1.f - 2.f * r1 * invm + r2 * invm * invm;
    }
}

// tens = cC1[i] + cC2[l] - 2*(csW[l] - (symP@W)[i,l]/mx); Km = exp(-tens/eps)
// grid: (6, NBH), block: (16,16)
__global__ void k_tens() {
    __shared__ float sW[SS * KD];     // 24 KB
    __shared__ float sP[64 * 65];     // 16.6 KB
    int bh = blockIdx.y, tile = blockIdx.x;
    int l = threadIdx.x, iy = threadIdx.y;
    int t = iy * 16 + l;

    for (int idx = t; idx < SS * KD; idx += 256) sW[idx] = g_W[bh * SS * KD + idx];

    float acc0 = 0.f, acc1 = 0.f, acc2 = 0.f, acc3 = 0.f;
    int i0 = tile * 64;
    const float* SPb = g_symP + bh * SS * SS;

    for (int s0 = 0; s0 < SS; s0 += 64) {
        __syncthreads();
        for (int idx = t; idx < 64 * 64; idx += 256) {
            int r = idx >> 6, ss = idx & 63;
            sP[r * 65 + ss] = SPb[(i0 + r) * SS + s0 + ss];
        }
        __syncthreads();
        #pragma unroll 4
        for (int ss = 0; ss < 64; ss++) {
            float wv = sW[(s0 + ss) * KD + l];
            acc0 += sP[(iy     ) * 65 + ss] * wv;
            acc1 += sP[(iy + 16) * 65 + ss] * wv;
            acc2 += sP[(iy + 32) * 65 + ss] * wv;
            acc3 += sP[(iy + 48) * 65 + ss] * wv;
        }
    }
    float invm = 1.f / fmaxf(__uint_as_float(g_mx[bh]), EPSF);
    float cc2  = g_cC2[bh * KD + l];
    float cs   = g_csW[bh * KD + l];
    const float inve = 1.f / GWEPS;
    float accs[4] = {acc0, acc1, acc2, acc3};
    #pragma unroll
    for (int r4 = 0; r4 < 4; r4++) {
        int i = i0 + iy + 16 * r4;
        float tens = g_cC1[bh * SS + i] + cc2 - 2.f * (cs - accs[r4] * invm);
        int oi = (bh * SS + i) * KD + l;
        g_tens[oi] = tens;
        g_Km[oi]   = __expf(-tens * inve);
    }
}

// sinkhorn (20 iters) entirely in smem; emits W=T*C2^T (+colsum) or alpha on last
// grid: NBH, block: 384
__global__ void k_sink(const float* __restrict__ DG, const float* __restrict__ bglob, int last) {
    __shared__ float sK[SS * 17];     // 26.1 KB, stride-17 pad
    __shared__ float sv[KD];
    __shared__ float sb[KD];
    __shared__ float sC2[KD * KD];
    __shared__ float wpart[12 * KD];
    __shared__ float wsum[12];

    int bh = blockIdx.x, i = threadIdx.x;
    int w = i / 32, lane = i % 32;

    const float4* Kb = reinterpret_cast<const float4*>(g_Km + bh * SS * KD);
    #pragma unroll
    for (int q = 0; q < 4; q++) {
        float4 v4 = Kb[i * 4 + q];
        sK[i * 17 + 4 * q + 0] = v4.x;
        sK[i * 17 + 4 * q + 1] = v4.y;
        sK[i * 17 + 4 * q + 2] = v4.z;
        sK[i * 17 + 4 * q + 3] = v4.w;
    }
    if (i < KD)       { sv[i] = 1.f; sb[i] = bglob[bh * KD + i]; }
    if (i < KD * KD)  sC2[i] = DG[bh * KD * KD + i];
    float a_i = g_a[bh * SS + i];
    __syncthreads();

    float u = 1.f;
    for (int it = 0; it < 20; it++) {
        float s = 0.f;
        #pragma unroll
        for (int k = 0; k < KD; k++) s += sK[i * 17 + k] * sv[k];
        u = a_i / fmaxf(s, 1e-30f);

        float p[KD];
        #pragma unroll
        for (int k = 0; k < KD; k++) p[k] = sK[i * 17 + k] * u;
        #pragma unroll
        for (int k = 0; k < KD; k++)
            #pragma unroll
            for (int off = 16; off; off >>= 1)
                p[k] += __shfl_down_sync(0xffffffffu, p[k], off);
        if (lane == 0) {
            #pragma unroll
            for (int k = 0; k < KD; k++) wpart[w * KD + k] = p[k];
        }
        __syncthreads();
        if (i < KD) {
            float sm = 0.f;
            #pragma unroll
            for (int ww = 0; ww < 12; ww++) sm += wpart[ww * KD + i];
            sv[i] = sb[i] / fmaxf(sm, 1e-30f);
        }
        __syncthreads();
    }

    float Trow[KD];
    #pragma unroll
    for (int k = 0; k < KD; k++) Trow[k] = u * sK[i * 17 + k] * sv[k];

    if (!last) {
        float Wr[KD];
        #pragma unroll
        for (int l = 0; l < KD; l++) {
            float s = 0.f;
            #pragma unroll
            for (int k = 0; k < KD; k++) s += Trow[k] * sC2[l * KD + k];
            Wr[l] = s;
        }
        float4* Wo = reinterpret_cast<float4*>(g_W + (bh * SS + i) * KD);
        Wo[0] = make_float4(Wr[0],  Wr[1],  Wr[2],  Wr[3]);
        Wo[1] = make_float4(Wr[4],  Wr[5],  Wr[6],  Wr[7]);
        Wo[2] = make_float4(Wr[8],  Wr[9],  Wr[10], Wr[11]);
        Wo[3] = make_float4(Wr[12], Wr[13], Wr[14], Wr[15]);
        // column sums of W -> g_csW
        #pragma unroll
        for (int k = 0; k < KD; k++)
            #pragma unroll
            for (int off = 16; off; off >>= 1)
                Wr[k] += __shfl_down_sync(0xffffffffu, Wr[k], off);
        if (lane == 0) {
            #pragma unroll
            for (int k = 0; k < KD; k++) wpart[w * KD + k] = Wr[k];
        }
        __syncthreads();
        if (i < KD) {
            float sm = 0.f;
            #pragma unroll
            for (int ww = 0; ww < 12; ww++) sm += wpart[ww * KD + i];
            g_csW[bh * KD + i] = sm;
        }
    } else {
        const float* tb = g_tens + (bh * SS + i) * KD;
        float g = 0.f;
        #pragma unroll
        for (int k = 0; k < KD; k++) g += tb[k] * Trow[k];
        #pragma unroll
        for (int off = 16; off; off >>= 1) g += __shfl_down_sync(0xffffffffu, g, off);
        if (lane == 0) wsum[w] = g;
        __syncthreads();
        if (i == 0) {
            float tot = 0.f;
            #pragma unroll
            for (int ww = 0; ww < 12; ww++) tot += wsum[ww];
            g_alpha[bh] = expf(-tot);      // sigma = 1
        }
    }
}

// v projection: vh[b,h,s,d] = sum_k nv[b,s,k]*vw[h*32+d,k] + vb
// grid: (193, 4), block: 256
__global__ void k_vproj(const float* __restrict__ nv, const float* __restrict__ vw,
                        const float* __restrict__ vb) {
    __shared__ float sA [64 * 33];
    __shared__ float sWt[64 * 33];
    int m0 = blockIdx.x * 64, n0 = blockIdx.y * 64;
    int t = threadIdx.x, tx = t % 16, ty = t / 16;
    float acc[4][4] = {};

    for (int k0 = 0; k0 < 256; k0 += 32) {
        __syncthreads();
        for (int idx = t; idx < 64 * 32; idx += 256) {
            int r = idx >> 5, kk = idx & 31;
            int m = m0 + r;
            sA [r * 33 + kk] = (m < NB * SS1) ? nv[m * 256 + k0 + kk] : 0.f;
            sWt[r * 33 + kk] = vw[(n0 + r) * 256 + k0 + kk];
        }
        __syncthreads();
        for (int kk = 0; kk < 32; kk++) {
            float ar[4], bc[4];
            #pragma unroll
            for (int r = 0; r < 4; r++) ar[r] = sA [(ty + 16 * r) * 33 + kk];
            #pragma unroll
            for (int c = 0; c < 4; c++) bc[c] = sWt[(tx + 16 * c) * 33 + kk];
            #pragma unroll
            for (int r = 0; r < 4; r++)
                #pragma unroll
                for (int c = 0; c < 4; c++) acc[r][c] += ar[r] * bc[c];
        }
    }
    #pragma unroll
    for (int r = 0; r < 4; r++) {
        int m = m0 + ty + 16 * r;
        if (m >= NB * SS1) continue;
        int b = m / SS1, s = m % SS1;
        #pragma unroll
        for (int c = 0; c < 4; c++) {
            int n = n0 + tx + 16 * c;
            int h = n >> 5, d = n & 31;
            g_vh[((b * NH + h) * SS1 + s) * 32 + d] = acc[r][c] + vb[n];
        }
    }
}

// attn row 0: [0]=0, [1..384]=1/384
__global__ void k_row0(float* __restrict__ attnOut) {
    int bh = blockIdx.x, t = threadIdx.x;
    float* row = attnOut + bh * SS1 * SS1;
    if (t == 0) row[0] = 0.f;
    float v = 1.f / 384.f;
    for (int j = t; j < SS; j += blockDim.x) row[1 + j] = v;
}

// rows 1..384: Q_hat = max(Q,eps)^(1+alpha), diag zeroed, row-normalized
// grid: (6, NBH), block: 256 (8 warps x 8 rows)
__global__ void k_attn(const float* __restrict__ priorQ, float* __restrict__ attnOut) {
    int bh = blockIdx.y, tile = blockIdx.x, t = threadIdx.x;
    int w = t / 32, lane = t % 32;
    float e = 1.f + g_alpha[bh];
    const float* Qb = priorQ + bh * SS * SS;
    float* Ab = attnOut + bh * SS1 * SS1;

    for (int rr = 0; rr < 8; rr++) {
        int r = tile * 64 + w * 8 + rr;
        const float* qrow = Qb + r * SS;
        float tv[12];
        float sum = 0.f;
        #pragma unroll
        for (int c = 0; c < 12; c++) {
            int m = lane + 32 * c;
            float q = fmaxf(qrow[m], EPSF);
            float x = __powf(q, e);
            if (m == r) x = 0.f;
            tv[c] = x;
            sum += x;
        }
        #pragma unroll
        for (int off = 16; off; off >>= 1) sum += __shfl_xor_sync(0xffffffffu, sum, off);
        float inv = 1.f / fmaxf(sum, EPSF);
        float* arow = Ab + (r + 1) * SS1;
        if (lane == 0) arow[0] = 0.f;
        #pragma unroll
        for (int c = 0; c < 12; c++) arow[1 + lane + 32 * c] = tv[c] * inv;
    }
}

// context: basis[b,i,h,d] = sum_j attn[bh,i,j] * vh[bh,j,d]
// grid: (7, NBH), block: 256 (tx=d 0..31, ty row group)
__global__ void k_ctx(const float* __restrict__ attnOut, float* __restrict__ outBasis) {
    __shared__ float sA[64 * 33];
    __shared__ float sV[32 * 33];
    int bh = blockIdx.y, tile = blockIdx.x, t = threadIdx.x;
    int tx = t % 32, ty = t / 32;
    float acc[8] = {};
    const float* Ab = attnOut + bh * SS1 * SS1;
    const float* Vb = g_vh + bh * SS1 * 32;
    int i0 = tile * 64;

    for (int j0 = 0; j0 < SS1; j0 += 32) {
        __syncthreads();
        for (int idx = t; idx < 64 * 32; idx += 256) {
            int r = idx >> 5, jj = idx & 31;
            int i = i0 + r, j = j0 + jj;
            sA[r * 33 + jj] = (i < SS1 && j < SS1) ? Ab[i * SS1 + j] : 0.f;
        }
        for (int idx = t; idx < 32 * 32; idx += 256) {
            int jj = idx >> 5, d = idx & 31;
            int j = j0 + jj;
            sV[jj * 33 + d] = (j < SS1) ? Vb[j * 32 + d] : 0.f;
        }
        __syncthreads();
        #pragma unroll 4
        for (int jj = 0; jj < 32; jj++) {
            float v = sV[jj * 33 + tx];
            #pragma unroll
            for (int r8 = 0; r8 < 8; r8++) acc[r8] += sA[(ty + 8 * r8) * 33 + jj] * v;
        }
    }
    int b = bh >> 3, h = bh & 7;
    #pragma unroll
    for (int r8 = 0; r8 < 8; r8++) {
        int i = i0 + ty + 8 * r8;
        if (i < SS1)
            outBasis[(b * SS1 + i) * 256 + h * 32 + tx] = acc[r8];
    }
}

// ---------------------------------------------------------------------------
extern "C" void kernel_launch(void* const* d_in, const int* in_sizes, int n_in,
                              void* d_out, int out_size) {
    const float* nv = (const float*)d_in[1];   // name_value_embeddings [32,385,256]
    const float* P  = (const float*)d_in[2];   // shared_attn [32,8,385,385]
    const float* Q  = (const float*)d_in[3];   // prior_Q [32,8,384,384]
    const float* DG = (const float*)d_in[4];   // [32,8,16,16]
    const float* bb = (const float*)d_in[5];   // [32,8,16]
    const float* vw = (const float*)d_in[6];   // [256,256]
    const float* vb = (const float*)d_in[7];   // [256]

    float* outB = (float*)d_out;                                   // basis [32,385,8,32]
    float* outA = (float*)d_out + (out_size - NBH * SS1 * SS1);    // attn  [32,8,385,385]

    k_zero   <<<(NBH * SS + 255) / 256, 256>>>();
    k_sym    <<<dim3(78, NBH), dim3(32, 32)>>>(P);
    k_scalars<<<NBH, 256>>>(DG, bb);
    k_cc1    <<<dim3(6, NBH), 256>>>();
    k_vproj  <<<dim3(193, 4), 256>>>(nv, vw, vb);

    for (int it = 0; it < 5; it++) {
        k_tens<<<dim3(6, NBH), dim3(16, 16)>>>();
        k_sink<<<NBH, 384>>>(DG, bb, it == 4 ? 1 : 0);
    }

    k_row0<<<NBH, 128>>>(outA);
    k_attn<<<dim3(6, NBH), 256>>>(Q, outA);
    k_ctx <<<dim3(7, NBH), 256>>>(outA, outB);
}

// round 15
// speedup vs baseline: 1.0114x; 1.0002x over previous
#include <cuda_runtime.h>

#define SS   384
#define SS1  385
#define NH   8
#define NB   32
#define NBH  256          // NB*NH
#define KD   16
#define EPSF 1e-8f
#define GWEPS 0.05f

// ---------------- scratch (static device globals; no allocations) ----------
__device__ float        g_symP[NBH * SS * SS];       // 151 MB
__device__ float        g_deg [NBH * SS];
__device__ unsigned int g_mx  [NBH];
__device__ float        g_a   [NBH * SS];
__device__ float        g_cC1 [NBH * SS];
__device__ float        g_cC2 [NBH * KD];
__device__ float        g_csW [NBH * KD];
__device__ float        g_W   [NBH * SS * KD];
__device__ float        g_tens[NBH * SS * KD];
__device__ float        g_Km  [NBH * SS * KD];
__device__ float        g_alpha[NBH];
__device__ float        g_vh  [NBH * SS1 * 32];

// ---------------------------------------------------------------------------
__global__ void k_zero() {
    int t = blockIdx.x * blockDim.x + threadIdx.x;
    if (t < NBH * SS) g_deg[t] = 0.f;
    if (t < NBH)      g_mx[t]  = 0u;
}

// symmetrize P[1:,1:] -> symP, accumulate rowsums (deg) and global max
// grid: (78 tile-pairs, NBH), block: (32,32)
__global__ void k_sym(const float* __restrict__ P) {
    __shared__ float sA[32][33];
    __shared__ float sB[32][33];
    __shared__ float wm[32];

    int bh = blockIdx.y;
    int p  = blockIdx.x;
    int ti = 0;
    while (p >= 12 - ti) { p -= 12 - ti; ti++; }
    int tj = ti + p;

    int x = threadIdx.x, y = threadIdx.y;
    const float* Pb = P + bh * SS1 * SS1;
    int r0 = ti * 32, c0 = tj * 32;

    sA[y][x] = Pb[(1 + r0 + y) * SS1 + 1 + c0 + x];
    sB[y][x] = Pb[(1 + c0 + y) * SS1 + 1 + r0 + x];
    __syncthreads();

    float* SPb = g_symP + bh * SS * SS;
    float symA = 0.5f * (sA[y][x] + sB[x][y]);
    float symB = 0.5f * (sB[y][x] + sA[x][y]);
    SPb[(r0 + y) * SS + c0 + x] = symA;
    SPb[(c0 + y) * SS + r0 + x] = symB;

    // row sums (deg): A-tile rows always, B-tile rows only if off-diagonal
    float rs = symA;
    #pragma unroll
    for (int off = 16; off; off >>= 1) rs += __shfl_down_sync(0xffffffffu, rs, off);
    if (x == 0) atomicAdd(&g_deg[bh * SS + r0 + y], rs);
    if (ti != tj) {
        float rs2 = symB;
        #pragma unroll
        for (int off = 16; off; off >>= 1) rs2 += __shfl_down_sync(0xffffffffu, rs2, off);
        if (x == 0) atomicAdd(&g_deg[bh * SS + c0 + y], rs2);
    }

    // block max of symA (B-tile values are the same set transposed)
    float m = symA;
    #pragma unroll
    for (int off = 16; off; off >>= 1) m = fmaxf(m, __shfl_down_sync(0xffffffffu, m, off));
    if (x == 0) wm[y] = m;
    __syncthreads();
    if (y == 0) {
        float mm = wm[x];
        #pragma unroll
        for (int off = 16; off; off >>= 1) mm = fmaxf(mm, __shfl_down_sync(0xffffffffu, mm, off));
        if (x == 0) atomicMax(&g_mx[bh], __float_as_uint(mm));
    }
}

// per-bh: a = deg/sum(deg); cC2[l]=sum_k b_k C2[k,l]^2; w0[l]=sum_k b_k C2[l,k];
// W0 = a (x) w0 ; csW0 = w0 * sum(a).   grid: NBH, block: 256
__global__ void k_scalars(const float* __restrict__ DG, const float* __restrict__ bb) {
    __shared__ float red[256];
    __shared__ float sw0[KD];
    int bh = blockIdx.x, t = threadIdx.x;

    float s = 0.f;
    for (int i = t; i < SS; i += 256) s += g_deg[bh * SS + i];
    red[t] = s; __syncthreads();
    for (int off = 128; off; off >>= 1) { if (t < off) red[t] += red[t + off]; __syncthreads(); }
    float sumdeg = red[0];
    float inv = 1.f / fmaxf(sumdeg, EPSF);
    float sa  = sumdeg * inv;          // == 1 unless degenerate

    for (int i = t; i < SS; i += 256) g_a[bh * SS + i] = g_deg[bh * SS + i] * inv;

    if (t < KD) {
        int l = t;
        float c2 = 0.f, w0 = 0.f;
        for (int k = 0; k < KD; k++) {
            float bk  = bb[bh * KD + k];
            float ckl = DG[bh * KD * KD + k * KD + l];
            float clk = DG[bh * KD * KD + l * KD + k];
            c2 += bk * ckl * ckl;
            w0 += bk * clk;
        }
        g_cC2[bh * KD + l] = c2;
        g_csW[bh * KD + l] = w0 * sa;
        sw0[l] = w0;
    }
    __syncthreads();
    for (int idx = t; idx < SS * KD; idx += 256) {
        int i = idx / KD, l = idx % KD;
        g_W[bh * SS * KD + idx] = g_a[bh * SS + i] * sw0[l];
    }
}

// cC1[i] = 1 - 2*r1/mx + r2/mx^2,  r1=sum symP*a, r2=sum symP^2*a
// grid: (6, NBH), block: 256 (8 warps x 8 rows)
__global__ void k_cc1() {
    __shared__ float sa[SS];
    int bh = blockIdx.y, tile = blockIdx.x, t = threadIdx.x;
    for (int i = t; i < SS; i += 256) sa[i] = g_a[bh * SS + i];
    __syncthreads();
    float invm = 1.f / fmaxf(__uint_as_float(g_mx[bh]), EPSF);
    int w = t / 32, lane = t % 32;
    const float* SPb = g_symP + bh * SS * SS;
    for (int rr = 0; rr < 8; rr++) {
        int row = tile * 64 + w * 8 + rr;
        const float* Pr = SPb + row * SS;
        float r1 = 0.f, r2 = 0.f;
        for (int s = lane; s < SS; s += 32) {
            float p = Pr[s], av = sa[s];
            r1 += p * av;
            r2 += p * p * av;
        }
        #pragma unroll
        for (int off = 16; off; off >>= 1) {
            r1 += __shfl_down_sync(0xffffffffu, r1, off);
            r2 += __shfl_down_sync(0xffffffffu, r2, off);
        }
        if (lane == 0)
            g_cC1[bh * SS + row] = 1.f - 2.f * r1 * invm + r2 * invm * invm;
    }
}

// tens = cC1[i] + cC2[l] - 2*(csW[l] - (symP@W)[i,l]/mx); Km = exp(-tens/eps)
// grid: (6, NBH), block: (16,16)
__global__ void k_tens() {
    __shared__ float sW[SS * KD];     // 24 KB
    __shared__ float sP[64 * 65];     // 16.6 KB
    int bh = blockIdx.y, tile = blockIdx.x;
    int l = threadIdx.x, iy = threadIdx.y;
    int t = iy * 16 + l;

    for (int idx = t; idx < SS * KD; idx += 256) sW[idx] = g_W[bh * SS * KD + idx];

    float acc0 = 0.f, acc1 = 0.f, acc2 = 0.f, acc3 = 0.f;
    int i0 = tile * 64;
    const float* SPb = g_symP + bh * SS * SS;

    for (int s0 = 0; s0 < SS; s0 += 64) {
        __syncthreads();
        for (int idx = t; idx < 64 * 64; idx += 256) {
            int r = idx >> 6, ss = idx & 63;
            sP[r * 65 + ss] = SPb[(i0 + r) * SS + s0 + ss];
        }
        __syncthreads();
        #pragma unroll 4
        for (int ss = 0; ss < 64; ss++) {
            float wv = sW[(s0 + ss) * KD + l];
            acc0 += sP[(iy     ) * 65 + ss] * wv;
            acc1 += sP[(iy + 16) * 65 + ss] * wv;
            acc2 += sP[(iy + 32) * 65 + ss] * wv;
            acc3 += sP[(iy + 48) * 65 + ss] * wv;
        }
    }
    float invm = 1.f / fmaxf(__uint_as_float(g_mx[bh]), EPSF);
    float cc2  = g_cC2[bh * KD + l];
    float cs   = g_csW[bh * KD + l];
    const float inve = 1.f / GWEPS;
    float accs[4] = {acc0, acc1, acc2, acc3};
    #pragma unroll
    for (int r4 = 0; r4 < 4; r4++) {
        int i = i0 + iy + 16 * r4;
        float tens = g_cC1[bh * SS + i] + cc2 - 2.f * (cs - accs[r4] * invm);
        int oi = (bh * SS + i) * KD + l;
        g_tens[oi] = tens;
        g_Km[oi]   = __expf(-tens * inve);
    }
}

// sinkhorn (20 iters) entirely in smem; emits W=T*C2^T (+colsum) or alpha on last
// grid: NBH, block: 384
__global__ void k_sink(const float* __restrict__ DG, const float* __restrict__ bglob, int last) {
    __shared__ float sK[SS * 17];     // 26.1 KB, stride-17 pad
    __shared__ float sv[KD];
    __shared__ float sb[KD];
    __shared__ float sC2[KD * KD];
    __shared__ float wpart[12 * KD];
    __shared__ float wsum[12];

    int bh = blockIdx.x, i = threadIdx.x;
    int w = i / 32, lane = i % 32;

    const float4* Kb = reinterpret_cast<const float4*>(g_Km + bh * SS * KD);
    #pragma unroll
    for (int q = 0; q < 4; q++) {
        float4 v4 = Kb[i * 4 + q];
        sK[i * 17 + 4 * q + 0] = v4.x;
        sK[i * 17 + 4 * q + 1] = v4.y;
        sK[i * 17 + 4 * q + 2] = v4.z;
        sK[i * 17 + 4 * q + 3] = v4.w;
    }
    if (i < KD)       { sv[i] = 1.f; sb[i] = bglob[bh * KD + i]; }
    if (i < KD * KD)  sC2[i] = DG[bh * KD * KD + i];
    float a_i = g_a[bh * SS + i];
    __syncthreads();

    float u = 1.f;
    for (int it = 0; it < 20; it++) {
        float s = 0.f;
        #pragma unroll
        for (int k = 0; k < KD; k++) s += sK[i * 17 + k] * sv[k];
        u = a_i / fmaxf(s, 1e-30f);

        float p[KD];
        #pragma unroll
        for (int k = 0; k < KD; k++) p[k] = sK[i * 17 + k] * u;
        #pragma unroll
        for (int k = 0; k < KD; k++)
            #pragma unroll
            for (int off = 16; off; off >>= 1)
                p[k] += __shfl_down_sync(0xffffffffu, p[k], off);
        if (lane == 0) {
            #pragma unroll
            for (int k = 0; k < KD; k++) wpart[w * KD + k] = p[k];
        }
        __syncthreads();
        if (i < KD) {
            float sm = 0.f;
            #pragma unroll
            for (int ww = 0; ww < 12; ww++) sm += wpart[ww * KD + i];
            sv[i] = sb[i] / fmaxf(sm, 1e-30f);
        }
        __syncthreads();
    }

    float Trow[KD];
    #pragma unroll
    for (int k = 0; k < KD; k++) Trow[k] = u * sK[i * 17 + k] * sv[k];

    if (!last) {
        float Wr[KD];
        #pragma unroll
        for (int l = 0; l < KD; l++) {
            float s = 0.f;
            #pragma unroll
            for (int k = 0; k < KD; k++) s += Trow[k] * sC2[l * KD + k];
            Wr[l] = s;
        }
        float4* Wo = reinterpret_cast<float4*>(g_W + (bh * SS + i) * KD);
        Wo[0] = make_float4(Wr[0],  Wr[1],  Wr[2],  Wr[3]);
        Wo[1] = make_float4(Wr[4],  Wr[5],  Wr[6],  Wr[7]);
        Wo[2] = make_float4(Wr[8],  Wr[9],  Wr[10], Wr[11]);
        Wo[3] = make_float4(Wr[12], Wr[13], Wr[14], Wr[15]);
        // column sums of W -> g_csW
        #pragma unroll
        for (int k = 0; k < KD; k++)
            #pragma unroll
            for (int off = 16; off; off >>= 1)
                Wr[k] += __shfl_down_sync(0xffffffffu, Wr[k], off);
        if (lane == 0) {
            #pragma unroll
            for (int k = 0; k < KD; k++) wpart[w * KD + k] = Wr[k];
        }
        __syncthreads();
        if (i < KD) {
            float sm = 0.f;
            #pragma unroll
            for (int ww = 0; ww < 12; ww++) sm += wpart[ww * KD + i];
            g_csW[bh * KD + i] = sm;
        }
    } else {
        const float* tb = g_tens + (bh * SS + i) * KD;
        float g = 0.f;
        #pragma unroll
        for (int k = 0; k < KD; k++) g += tb[k] * Trow[k];
        #pragma unroll
        for (int off = 16; off; off >>= 1) g += __shfl_down_sync(0xffffffffu, g, off);
        if (lane == 0) wsum[w] = g;
        __syncthreads();
        if (i == 0) {
            float tot = 0.f;
            #pragma unroll
            for (int ww = 0; ww < 12; ww++) tot += wsum[ww];
            g_alpha[bh] = expf(-tot);      // sigma = 1
        }
    }
}

// v projection: vh[b,h,s,d] = sum_k nv[b,s,k]*vw[h*32+d,k] + vb
// grid: (193, 4), block: 256
__global__ void k_vproj(const float* __restrict__ nv, const float* __restrict__ vw,
                        const float* __restrict__ vb) {
    __shared__ float sA [64 * 33];
    __shared__ float sWt[64 * 33];
    int m0 = blockIdx.x * 64, n0 = blockIdx.y * 64;
    int t = threadIdx.x, tx = t % 16, ty = t / 16;
    float acc[4][4] = {};

    for (int k0 = 0; k0 < 256; k0 += 32) {
        __syncthreads();
        for (int idx = t; idx < 64 * 32; idx += 256) {
            int r = idx >> 5, kk = idx & 31;
            int m = m0 + r;
            sA [r * 33 + kk] = (m < NB * SS1) ? nv[m * 256 + k0 + kk] : 0.f;
            sWt[r * 33 + kk] = vw[(n0 + r) * 256 + k0 + kk];
        }
        __syncthreads();
        for (int kk = 0; kk < 32; kk++) {
            float ar[4], bc[4];
            #pragma unroll
            for (int r = 0; r < 4; r++) ar[r] = sA [(ty + 16 * r) * 33 + kk];
            #pragma unroll
            for (int c = 0; c < 4; c++) bc[c] = sWt[(tx + 16 * c) * 33 + kk];
            #pragma unroll
            for (int r = 0; r < 4; r++)
                #pragma unroll
                for (int c = 0; c < 4; c++) acc[r][c] += ar[r] * bc[c];
        }
    }
    #pragma unroll
    for (int r = 0; r < 4; r++) {
        int m = m0 + ty + 16 * r;
        if (m >= NB * SS1) continue;
        int b = m / SS1, s = m % SS1;
        #pragma unroll
        for (int c = 0; c < 4; c++) {
            int n = n0 + tx + 16 * c;
            int h = n >> 5, d = n & 31;
            g_vh[((b * NH + h) * SS1 + s) * 32 + d] = acc[r][c] + vb[n];
        }
    }
}

// attn row 0: [0]=0, [1..384]=1/384
__global__ void k_row0(float* __restrict__ attnOut) {
    int bh = blockIdx.x, t = threadIdx.x;
    float* row = attnOut + bh * SS1 * SS1;
    if (t == 0) row[0] = 0.f;
    float v = 1.f / 384.f;
    for (int j = t; j < SS; j += blockDim.x) row[1 + j] = v;
}

// rows 1..384: Q_hat = max(Q,eps)^(1+alpha), diag zeroed, row-normalized
// grid: (6, NBH), block: 256 (8 warps x 8 rows)
__global__ void k_attn(const float* __restrict__ priorQ, float* __restrict__ attnOut) {
    int bh = blockIdx.y, tile = blockIdx.x, t = threadIdx.x;
    int w = t / 32, lane = t % 32;
    float e = 1.f + g_alpha[bh];
    const float* Qb = priorQ + bh * SS * SS;
    float* Ab = attnOut + bh * SS1 * SS1;

    for (int rr = 0; rr < 8; rr++) {
        int r = tile * 64 + w * 8 + rr;
        const float* qrow = Qb + r * SS;
        float tv[12];
        float sum = 0.f;
        #pragma unroll
        for (int c = 0; c < 12; c++) {
            int m = lane + 32 * c;
            float q = fmaxf(qrow[m], EPSF);
            float x = __powf(q, e);
            if (m == r) x = 0.f;
            tv[c] = x;
            sum += x;
        }
        #pragma unroll
        for (int off = 16; off; off >>= 1) sum += __shfl_xor_sync(0xffffffffu, sum, off);
        float inv = 1.f / fmaxf(sum, EPSF);
        float* arow = Ab + (r + 1) * SS1;
        if (lane == 0) arow[0] = 0.f;
        #pragma unroll
        for (int c = 0; c < 12; c++) arow[1 + lane + 32 * c] = tv[c] * inv;
    }
}

// context: basis[b,i,h,d] = sum_j attn[bh,i,j] * vh[bh,j,d]
// grid: (7, NBH), block: 256 (tx=d 0..31, ty row group)
__global__ void k_ctx(const float* __restrict__ attnOut, float* __restrict__ outBasis) {
    __shared__ float sA[64 * 33];
    __shared__ float sV[32 * 33];
    int bh = blockIdx.y, tile = blockIdx.x, t = threadIdx.x;
    int tx = t % 32, ty = t / 32;
    float acc[8] = {};
    const float* Ab = attnOut + bh * SS1 * SS1;
    const float* Vb = g_vh + bh * SS1 * 32;
    int i0 = tile * 64;

    for (int j0 = 0; j0 < SS1; j0 += 32) {
        __syncthreads();
        for (int idx = t; idx < 64 * 32; idx += 256) {
            int r = idx >> 5, jj = idx & 31;
            int i = i0 + r, j = j0 + jj;
            sA[r * 33 + jj] = (i < SS1 && j < SS1) ? Ab[i * SS1 + j] : 0.f;
        }
        for (int idx = t; idx < 32 * 32; idx += 256) {
            int jj = idx >> 5, d = idx & 31;
            int j = j0 + jj;
            sV[jj * 33 + d] = (j < SS1) ? Vb[j * 32 + d] : 0.f;
        }
        __syncthreads();
        #pragma unroll 4
        for (int jj = 0; jj < 32; jj++) {
            float v = sV[jj * 33 + tx];
            #pragma unroll
            for (int r8 = 0; r8 < 8; r8++) acc[r8] += sA[(ty + 8 * r8) * 33 + jj] * v;
        }
    }
    int b = bh >> 3, h = bh & 7;
    #pragma unroll
    for (int r8 = 0; r8 < 8; r8++) {
        int i = i0 + ty + 8 * r8;
        if (i < SS1)
            outBasis[(b * SS1 + i) * 256 + h * 32 + tx] = acc[r8];
    }
}

// ---------------------------------------------------------------------------
extern "C" void kernel_launch(void* const* d_in, const int* in_sizes, int n_in,
                              void* d_out, int out_size) {
    const float* nv = (const float*)d_in[1];   // name_value_embeddings [32,385,256]
    const float* P  = (const float*)d_in[2];   // shared_attn [32,8,385,385]
    const float* Q  = (const float*)d_in[3];   // prior_Q [32,8,384,384]
    const float* DG = (const float*)d_in[4];   // [32,8,16,16]
    const float* bb = (const float*)d_in[5];   // [32,8,16]
    const float* vw = (const float*)d_in[6];   // [256,256]
    const float* vb = (const float*)d_in[7];   // [256]

    float* outB = (float*)d_out;                                   // basis [32,385,8,32]
    float* outA = (float*)d_out + (out_size - NBH * SS1 * SS1);    // attn  [32,8,385,385]

    k_zero   <<<(NBH * SS + 255) / 256, 256>>>();
    k_sym    <<<dim3(78, NBH), dim3(32, 32)>>>(P);
    k_scalars<<<NBH, 256>>>(DG, bb);
    k_cc1    <<<dim3(6, NBH), 256>>>();
    k_vproj  <<<dim3(193, 4), 256>>>(nv, vw, vb);

    for (int it = 0; it < 5; it++) {
        k_tens<<<dim3(6, NBH), dim3(16, 16)>>>();
        k_sink<<<NBH, 384>>>(DG, bb, it == 4 ? 1 : 0);
    }

    k_row0<<<NBH, 128>>>(outA);
    k_attn<<<dim3(6, NBH), 256>>>(Q, outA);
    k_ctx <<<dim3(7, NBH), 256>>>(outA, outB);
}

// round 16
// speedup vs baseline: 1.6066x; 1.5885x over previous
#include <cuda_runtime.h>

#define SS   384
#define SS1  385
#define NH   8
#define NB   32
#define NBH  256          // NB*NH
#define KD   16
#define EPSF 1e-8f
#define GWEPS 0.05f

typedef unsigned long long ull;

// packed f32x2 FMA (Blackwell): acc = a*b + acc on both lanes
#define FMAX2(acc, a, b) \
    asm("fma.rn.f32x2 %0, %1, %2, %0;" : "+l"(acc) : "l"(a), "l"(b))
#define UNPX2(lo, hi, v) \
    asm("mov.b64 {%0,%1}, %2;" : "=f"(lo), "=f"(hi) : "l"(v))

// ---------------- scratch (static device globals; no allocations) ----------
__device__ float        g_symP[NBH * SS * SS];       // 151 MB
__device__ float        g_deg [NBH * SS];
__device__ unsigned int g_mx  [NBH];
__device__ float        g_a   [NBH * SS];
__device__ float        g_cC1 [NBH * SS];
__device__ float        g_cC2 [NBH * KD];
__device__ float        g_w0  [NBH * KD];
__device__ float        g_csW [NBH * KD];
__device__ float        g_W   [NBH * SS * KD];
__device__ float        g_tens[NBH * SS * KD];
__device__ float        g_Km  [NBH * SS * KD];
__device__ float        g_alpha[NBH];
__device__ float        g_vh  [NBH * SS1 * 32];

// ---------------------------------------------------------------------------
__global__ void k_zero() {
    int t = blockIdx.x * blockDim.x + threadIdx.x;
    if (t < NBH * SS) g_deg[t] = 0.f;
    if (t < NBH)      g_mx[t]  = 0u;
}

// symmetrize P[1:,1:] -> symP, accumulate rowsums (deg) and global max
// grid: (78 tile-pairs, NBH), block: (32,32)
__global__ void k_sym(const float* __restrict__ P) {
    __shared__ float sA[32][33];
    __shared__ float sB[32][33];
    __shared__ float wm[32];

    int bh = blockIdx.y;
    int p  = blockIdx.x;
    int ti = 0;
    while (p >= 12 - ti) { p -= 12 - ti; ti++; }
    int tj = ti + p;

    int x = threadIdx.x, y = threadIdx.y;
    const float* Pb = P + (size_t)bh * SS1 * SS1;
    int r0 = ti * 32, c0 = tj * 32;

    sA[y][x] = Pb[(1 + r0 + y) * SS1 + 1 + c0 + x];
    sB[y][x] = Pb[(1 + c0 + y) * SS1 + 1 + r0 + x];
    __syncthreads();

    float* SPb = g_symP + (size_t)bh * SS * SS;
    float symA = 0.5f * (sA[y][x] + sB[x][y]);
    float symB = 0.5f * (sB[y][x] + sA[x][y]);
    SPb[(r0 + y) * SS + c0 + x] = symA;
    SPb[(c0 + y) * SS + r0 + x] = symB;

    float rs = symA;
    #pragma unroll
    for (int off = 16; off; off >>= 1) rs += __shfl_down_sync(0xffffffffu, rs, off);
    if (x == 0) atomicAdd(&g_deg[bh * SS + r0 + y], rs);
    if (ti != tj) {
        float rs2 = symB;
        #pragma unroll
        for (int off = 16; off; off >>= 1) rs2 += __shfl_down_sync(0xffffffffu, rs2, off);
        if (x == 0) atomicAdd(&g_deg[bh * SS + c0 + y], rs2);
    }

    float m = symA;
    #pragma unroll
    for (int off = 16; off; off >>= 1) m = fmaxf(m, __shfl_down_sync(0xffffffffu, m, off));
    if (x == 0) wm[y] = m;
    __syncthreads();
    if (y == 0) {
        float mm = wm[x];
        #pragma unroll
        for (int off = 16; off; off >>= 1) mm = fmaxf(mm, __shfl_down_sync(0xffffffffu, mm, off));
        if (x == 0) atomicMax(&g_mx[bh], __float_as_uint(mm));
    }
}

// per-bh: a = deg/sum(deg); cC2[l]=sum_k b_k C2[k,l]^2; w0[l]=sum_k b_k C2[l,k];
// csW0 = w0 * sum(a).  grid: NBH, block: 256
__global__ void k_scalars(const float* __restrict__ DG, const float* __restrict__ bb) {
    __shared__ float red[256];
    int bh = blockIdx.x, t = threadIdx.x;

    float s = 0.f;
    for (int i = t; i < SS; i += 256) s += g_deg[bh * SS + i];
    red[t] = s; __syncthreads();
    for (int off = 128; off; off >>= 1) { if (t < off) red[t] += red[t + off]; __syncthreads(); }
    float sumdeg = red[0];
    float inv = 1.f / fmaxf(sumdeg, EPSF);
    float sa  = sumdeg * inv;

    for (int i = t; i < SS; i += 256) g_a[bh * SS + i] = g_deg[bh * SS + i] * inv;

    if (t < KD) {
        int l = t;
        float c2 = 0.f, w0 = 0.f;
        #pragma unroll
        for (int k = 0; k < KD; k++) {
            float bk  = bb[bh * KD + k];
            float ckl = DG[bh * KD * KD + k * KD + l];
            float clk = DG[bh * KD * KD + l * KD + k];
            c2 += bk * ckl * ckl;
            w0 += bk * clk;
        }
        g_cC2[bh * KD + l] = c2;
        g_w0 [bh * KD + l] = w0;
        g_csW[bh * KD + l] = w0 * sa;
    }
}

// fused cc1 + iteration-0 tens/Km (T0 = a (x) b is rank-1):
// r1 = sum symP*a; r2 = sum symP^2*a; cc1 = 1 - 2 r1/mx + r2/mx^2
// Km0[i,l] = exp(-(cc1 + cC2[l] - 2*(csW0[l] - r1*w0[l]/mx))/eps)
// grid: (6, NBH), block: 256 (8 warps x 8 rows)
__global__ void k_tens0() {
    __shared__ float4 sa4[96];
    __shared__ float w0s[KD], c2s[KD], css[KD];
    int bh = blockIdx.y, tile = blockIdx.x, t = threadIdx.x;
    if (t < 96) sa4[t] = ((const float4*)(g_a + bh * SS))[t];
    if (t >= 128 && t < 128 + KD) {
        int l = t - 128;
        w0s[l] = g_w0[bh * KD + l];
        c2s[l] = g_cC2[bh * KD + l];
        css[l] = g_csW[bh * KD + l];
    }
    __syncthreads();
    float invm = 1.f / fmaxf(__uint_as_float(g_mx[bh]), EPSF);
    int w = t >> 5, lane = t & 31;
    const float* SPb = g_symP + (size_t)bh * SS * SS;
    const float inve = 1.f / GWEPS;

    for (int rr = 0; rr < 8; rr++) {
        int row = tile * 64 + w * 8 + rr;
        const float4* Pr4 = (const float4*)(SPb + (size_t)row * SS);
        float r1 = 0.f, r2 = 0.f;
        #pragma unroll
        for (int c = 0; c < 3; c++) {
            int m4 = lane + 32 * c;
            float4 p = Pr4[m4];
            float4 a = sa4[m4];
            r1 = fmaf(p.x, a.x, fmaf(p.y, a.y, fmaf(p.z, a.z, fmaf(p.w, a.w, r1))));
            r2 = fmaf(p.x * p.x, a.x, fmaf(p.y * p.y, a.y,
                 fmaf(p.z * p.z, a.z, fmaf(p.w * p.w, a.w, r2))));
        }
        #pragma unroll
        for (int off = 16; off; off >>= 1) {
            r1 += __shfl_xor_sync(0xffffffffu, r1, off);
            r2 += __shfl_xor_sync(0xffffffffu, r2, off);
        }
        float cc1 = 1.f - 2.f * r1 * invm + r2 * invm * invm;
        if (lane == 16) g_cC1[bh * SS + row] = cc1;
        if (lane < KD) {
            float tens = cc1 + c2s[lane] - 2.f * (css[lane] - r1 * w0s[lane] * invm);
            g_Km[(size_t)(bh * SS + row) * KD + lane] = __expf(-tens * inve);
        }
    }
}

// GW tens pass, iterations 1..4: acc = symP @ W with f32x2 pairing over s
// grid: (6, NBH), block: 128.  thread: lq=t&3 -> 4 l's; rg=t>>2 -> rows 2rg,2rg+1
#define WTSTR 394
#define PSTR  66
__global__ void k_tens(int wrTens) {
    __shared__ __align__(16) float sWT[KD * WTSTR];   // transposed W [l][s]
    __shared__ __align__(16) float sP [64 * PSTR];
    int bh = blockIdx.y, tile = blockIdx.x, t = threadIdx.x;
    int lq = t & 3, rg = t >> 2;

    for (int idx = t; idx < SS * KD; idx += 128) {
        int s = idx >> 4, l = idx & 15;
        sWT[l * WTSTR + s] = g_W[(size_t)bh * SS * KD + idx];
    }

    ull acc0[4] = {0,0,0,0}, acc1[4] = {0,0,0,0};
    const float* SPb = g_symP + (size_t)bh * SS * SS + (size_t)(tile * 64) * SS;

    for (int s0 = 0; s0 < SS; s0 += 64) {
        __syncthreads();
        for (int idx = t; idx < 64 * 16; idx += 128) {
            int r = idx >> 4, c4 = idx & 15;
            float4 v = *(const float4*)(SPb + (size_t)r * SS + s0 + c4 * 4);
            float2* d = (float2*)&sP[r * PSTR + c4 * 4];
            d[0] = make_float2(v.x, v.y);
            d[1] = make_float2(v.z, v.w);
        }
        __syncthreads();
        const float* p0r = &sP[(2 * rg) * PSTR];
        const float* p1r = &sP[(2 * rg + 1) * PSTR];
        const float* wb  = &sWT[lq * 4 * WTSTR + s0];
        #pragma unroll 8
        for (int ss = 0; ss < 64; ss += 2) {
            ull pp0 = *(const ull*)(p0r + ss);
            ull pp1 = *(const ull*)(p1r + ss);
            #pragma unroll
            for (int j = 0; j < 4; j++) {
                ull ww = *(const ull*)(wb + j * WTSTR + ss);
                FMAX2(acc0[j], pp0, ww);
                FMAX2(acc1[j], pp1, ww);
            }
        }
    }

    float invm = 1.f / fmaxf(__uint_as_float(g_mx[bh]), EPSF);
    const float inve = 1.f / GWEPS;
    int i = tile * 64 + 2 * rg;
    float cc1a = g_cC1[bh * SS + i];
    float cc1b = g_cC1[bh * SS + i + 1];
    float t0[4], t1[4], k0[4], k1[4];
    #pragma unroll
    for (int j = 0; j < 4; j++) {
        int l = lq * 4 + j;
        float c2 = g_cC2[bh * KD + l];
        float cs = g_csW[bh * KD + l];
        float lo, hi;
        UNPX2(lo, hi, acc0[j]);
        float a0 = lo + hi;
        UNPX2(lo, hi, acc1[j]);
        float a1 = lo + hi;
        t0[j] = cc1a + c2 - 2.f * (cs - a0 * invm);
        t1[j] = cc1b + c2 - 2.f * (cs - a1 * invm);
        k0[j] = __expf(-t0[j] * inve);
        k1[j] = __expf(-t1[j] * inve);
    }
    size_t o0 = (size_t)(bh * SS + i) * KD + lq * 4;
    size_t o1 = o0 + KD;
    *(float4*)(g_Km + o0) = make_float4(k0[0], k0[1], k0[2], k0[3]);
    *(float4*)(g_Km + o1) = make_float4(k1[0], k1[1], k1[2], k1[3]);
    if (wrTens) {
        *(float4*)(g_tens + o0) = make_float4(t0[0], t0[1], t0[2], t0[3]);
        *(float4*)(g_tens + o1) = make_float4(t1[0], t1[1], t1[2], t1[3]);
    }
}

// sinkhorn (20 iters); K-row register-resident; colsums via 256-thread partials
// grid: NBH, block: 384
__global__ void k_sink(const float* __restrict__ DG, const float* __restrict__ bglob, int last) {
    __shared__ __align__(16) float sK[SS * 20];   // stride-20 rows (16B aligned)
    __shared__ float su[SS];
    __shared__ __align__(16) float4 sv4[4];
    __shared__ float sb[KD];
    __shared__ float sC2[KD * KD];
    __shared__ float part[16 * KD];
    __shared__ float wpart[12 * KD];
    __shared__ float wsum[12];

    int bh = blockIdx.x, i = threadIdx.x;
    int w = i >> 5, lane = i & 31;

    const float4* Kb = (const float4*)(g_Km + (size_t)bh * SS * KD);
    float4* sK4 = (float4*)sK;
    float4 kv[4];
    #pragma unroll
    for (int q = 0; q < 4; q++) { kv[q] = Kb[i * 4 + q]; sK4[i * 5 + q] = kv[q]; }
    if (i < KD)      { ((float*)sv4)[i] = 1.f; sb[i] = bglob[bh * KD + i]; }
    if (i < KD * KD) sC2[i] = DG[bh * KD * KD + i];
    float a_i = g_a[bh * SS + i];
    __syncthreads();

    float u = 1.f;
    for (int it = 0; it < 20; it++) {
        float4 v0 = sv4[0], v1 = sv4[1], v2 = sv4[2], v3 = sv4[3];
        float s = fmaf(kv[0].x, v0.x, fmaf(kv[0].y, v0.y, fmaf(kv[0].z, v0.z, kv[0].w * v0.w)))
                + fmaf(kv[1].x, v1.x, fmaf(kv[1].y, v1.y, fmaf(kv[1].z, v1.z, kv[1].w * v1.w)))
                + fmaf(kv[2].x, v2.x, fmaf(kv[2].y, v2.y, fmaf(kv[2].z, v2.z, kv[2].w * v2.w)))
                + fmaf(kv[3].x, v3.x, fmaf(kv[3].y, v3.y, fmaf(kv[3].z, v3.z, kv[3].w * v3.w)));
        u = a_i / fmaxf(s, 1e-30f);
        su[i] = u;
        __syncthreads();
        if (i < 256) {
            int k = i & 15, seg = i >> 4;
            const float* col = &sK[(seg * 24) * 20 + k];
            const float* sup = &su[seg * 24];
            float p = 0.f;
            #pragma unroll
            for (int r = 0; r < 24; r++) p = fmaf(col[r * 20], sup[r], p);
            part[seg * KD + k] = p;
        }
        __syncthreads();
        if (i < KD) {
            float sm = 0.f;
            #pragma unroll
            for (int sg = 0; sg < 16; sg++) sm += part[sg * KD + i];
            ((float*)sv4)[i] = sb[i] / fmaxf(sm, 1e-30f);
        }
        __syncthreads();
    }

    float tr[KD];
    #pragma unroll
    for (int q = 0; q < 4; q++) {
        float4 vv = sv4[q];
        tr[4 * q + 0] = u * kv[q].x * vv.x;
        tr[4 * q + 1] = u * kv[q].y * vv.y;
        tr[4 * q + 2] = u * kv[q].z * vv.z;
        tr[4 * q + 3] = u * kv[q].w * vv.w;
    }

    if (!last) {
        float Wr[KD];
        #pragma unroll
        for (int l = 0; l < KD; l++) {
            float s = 0.f;
            #pragma unroll
            for (int k = 0; k < KD; k++) s = fmaf(tr[k], sC2[l * KD + k], s);
            Wr[l] = s;
        }
        float4* Wo = (float4*)(g_W + (size_t)(bh * SS + i) * KD);
        Wo[0] = make_float4(Wr[0],  Wr[1],  Wr[2],  Wr[3]);
        Wo[1] = make_float4(Wr[4],  Wr[5],  Wr[6],  Wr[7]);
        Wo[2] = make_float4(Wr[8],  Wr[9],  Wr[10], Wr[11]);
        Wo[3] = make_float4(Wr[12], Wr[13], Wr[14], Wr[15]);
        #pragma unroll
        for (int k = 0; k < KD; k++)
            #pragma unroll
            for (int off = 16; off; off >>= 1)
                Wr[k] += __shfl_down_sync(0xffffffffu, Wr[k], off);
        if (lane == 0) {
            #pragma unroll
            for (int k = 0; k < KD; k++) wpart[w * KD + k] = Wr[k];
        }
        __syncthreads();
        if (i < KD) {
            float sm = 0.f;
            #pragma unroll
            for (int ww = 0; ww < 12; ww++) sm += wpart[ww * KD + i];
            g_csW[bh * KD + i] = sm;
        }
    } else {
        const float4* tb = (const float4*)(g_tens + (size_t)(bh * SS + i) * KD);
        float g = 0.f;
        #pragma unroll
        for (int q = 0; q < 4; q++) {
            float4 tv = tb[q];
            g = fmaf(tv.x, tr[4*q+0], fmaf(tv.y, tr[4*q+1],
                fmaf(tv.z, tr[4*q+2], fmaf(tv.w, tr[4*q+3], g))));
        }
        #pragma unroll
        for (int off = 16; off; off >>= 1) g += __shfl_down_sync(0xffffffffu, g, off);
        if (lane == 0) wsum[w] = g;
        __syncthreads();
        if (i == 0) {
            float tot = 0.f;
            #pragma unroll
            for (int ww = 0; ww < 12; ww++) tot += wsum[ww];
            g_alpha[bh] = expf(-tot);      // sigma = 1
        }
    }
}

// v projection: vh[b,h,s,d] = sum_k nv[b,s,k]*vw[h*32+d,k] + vb
// grid: (193, 4), block: 256
__global__ void k_vproj(const float* __restrict__ nv, const float* __restrict__ vw,
                        const float* __restrict__ vb) {
    __shared__ float sA [64 * 33];
    __shared__ float sWt[64 * 33];
    int m0 = blockIdx.x * 64, n0 = blockIdx.y * 64;
    int t = threadIdx.x, tx = t % 16, ty = t / 16;
    float acc[4][4] = {};

    for (int k0 = 0; k0 < 256; k0 += 32) {
        __syncthreads();
        for (int idx = t; idx < 64 * 32; idx += 256) {
            int r = idx >> 5, kk = idx & 31;
            int m = m0 + r;
            sA [r * 33 + kk] = (m < NB * SS1) ? nv[(size_t)m * 256 + k0 + kk] : 0.f;
            sWt[r * 33 + kk] = vw[(n0 + r) * 256 + k0 + kk];
        }
        __syncthreads();
        for (int kk = 0; kk < 32; kk++) {
            float ar[4], bc[4];
            #pragma unroll
            for (int r = 0; r < 4; r++) ar[r] = sA [(ty + 16 * r) * 33 + kk];
            #pragma unroll
            for (int c = 0; c < 4; c++) bc[c] = sWt[(tx + 16 * c) * 33 + kk];
            #pragma unroll
            for (int r = 0; r < 4; r++)
                #pragma unroll
                for (int c = 0; c < 4; c++) acc[r][c] += ar[r] * bc[c];
        }
    }
    #pragma unroll
    for (int r = 0; r < 4; r++) {
        int m = m0 + ty + 16 * r;
        if (m >= NB * SS1) continue;
        int b = m / SS1, s = m % SS1;
        #pragma unroll
        for (int c = 0; c < 4; c++) {
            int n = n0 + tx + 16 * c;
            int h = n >> 5, d = n & 31;
            g_vh[((b * NH + h) * SS1 + s) * 32 + d] = acc[r][c] + vb[n];
        }
    }
}

// attn row 0: [0]=0, [1..384]=1/384
__global__ void k_row0(float* __restrict__ attnOut) {
    int bh = blockIdx.x, t = threadIdx.x;
    float* row = attnOut + (size_t)bh * SS1 * SS1;
    if (t == 0) row[0] = 0.f;
    float v = 1.f / 384.f;
    for (int j = t; j < SS; j += blockDim.x) row[1 + j] = v;
}

// rows 1..384: Q_hat = max(Q,eps)^(1+alpha), diag zeroed, row-normalized
// grid: (6, NBH), block: 256 (8 warps x 8 rows)
__global__ void k_attn(const float* __restrict__ priorQ, float* __restrict__ attnOut) {
    int bh = blockIdx.y, tile = blockIdx.x, t = threadIdx.x;
    int w = t / 32, lane = t % 32;
    float e = 1.f + g_alpha[bh];
    const float* Qb = priorQ + (size_t)bh * SS * SS;
    float* Ab = attnOut + (size_t)bh * SS1 * SS1;

    for (int rr = 0; rr < 8; rr++) {
        int r = tile * 64 + w * 8 + rr;
        const float* qrow = Qb + (size_t)r * SS;
        float tv[12];
        float sum = 0.f;
        #pragma unroll
        for (int c = 0; c < 12; c++) {
            int m = lane + 32 * c;
            float q = fmaxf(qrow[m], EPSF);
            float x = __powf(q, e);
            if (m == r) x = 0.f;
            tv[c] = x;
            sum += x;
        }
        #pragma unroll
        for (int off = 16; off; off >>= 1) sum += __shfl_xor_sync(0xffffffffu, sum, off);
        float inv = 1.f / fmaxf(sum, EPSF);
        float* arow = Ab + (size_t)(r + 1) * SS1;
        if (lane == 0) arow[0] = 0.f;
        #pragma unroll
        for (int c = 0; c < 12; c++) arow[1 + lane + 32 * c] = tv[c] * inv;
    }
}

// context: basis[b,i,h,d] = sum_j attn[bh,i,j] * vh[bh,j,d]
// grid: (7, NBH), block: 256
__global__ void k_ctx(const float* __restrict__ attnOut, float* __restrict__ outBasis) {
    __shared__ float sA[64 * 33];
    __shared__ float sV[32 * 33];
    int bh = blockIdx.y, tile = blockIdx.x, t = threadIdx.x;
    int tx = t % 32, ty = t / 32;
    float acc[8] = {};
    const float* Ab = attnOut + (size_t)bh * SS1 * SS1;
    const float* Vb = g_vh + (size_t)bh * SS1 * 32;
    int i0 = tile * 64;

    for (int j0 = 0; j0 < SS1; j0 += 32) {
        __syncthreads();
        for (int idx = t; idx < 64 * 32; idx += 256) {
            int r = idx >> 5, jj = idx & 31;
            int i = i0 + r, j = j0 + jj;
            sA[r * 33 + jj] = (i < SS1 && j < SS1) ? Ab[(size_t)i * SS1 + j] : 0.f;
        }
        for (int idx = t; idx < 32 * 32; idx += 256) {
            int jj = idx >> 5, d = idx & 31;
            int j = j0 + jj;
            sV[jj * 33 + d] = (j < SS1) ? Vb[j * 32 + d] : 0.f;
        }
        __syncthreads();
        #pragma unroll 4
        for (int jj = 0; jj < 32; jj++) {
            float v = sV[jj * 33 + tx];
            #pragma unroll
            for (int r8 = 0; r8 < 8; r8++) acc[r8] += sA[(ty + 8 * r8) * 33 + jj] * v;
        }
    }
    int b = bh >> 3, h = bh & 7;
    #pragma unroll
    for (int r8 = 0; r8 < 8; r8++) {
        int i = i0 + ty + 8 * r8;
        if (i < SS1)
            outBasis[((size_t)(b * SS1 + i)) * 256 + h * 32 + tx] = acc[r8];
    }
}

// ---------------------------------------------------------------------------
extern "C" void kernel_launch(void* const* d_in, const int* in_sizes, int n_in,
                              void* d_out, int out_size) {
    const float* nv = (const float*)d_in[1];   // name_value_embeddings [32,385,256]
    const float* P  = (const float*)d_in[2];   // shared_attn [32,8,385,385]
    const float* Q  = (const float*)d_in[3];   // prior_Q [32,8,384,384]
    const float* DG = (const float*)d_in[4];   // [32,8,16,16]
    const float* bb = (const float*)d_in[5];   // [32,8,16]
    const float* vw = (const float*)d_in[6];   // [256,256]
    const float* vb = (const float*)d_in[7];   // [256]

    float* outB = (float*)d_out;                                   // basis [32,385,8,32]
    float* outA = (float*)d_out + (out_size - NBH * SS1 * SS1);    // attn  [32,8,385,385]

    k_zero   <<<(NBH * SS + 255) / 256, 256>>>();
    k_sym    <<<dim3(78, NBH), dim3(32, 32)>>>(P);
    k_scalars<<<NBH, 256>>>(DG, bb);
    k_vproj  <<<dim3(193, 4), 256>>>(nv, vw, vb);

    // GW outer iteration 0: fused cc1 + rank-1 tens
    k_tens0<<<dim3(6, NBH), 256>>>();
    k_sink <<<NBH, 384>>>(DG, bb, 0);
    // iterations 1..4
    for (int it = 1; it < 5; it++) {
        k_tens<<<dim3(6, NBH), 128>>>(it == 4 ? 1 : 0);
        k_sink<<<NBH, 384>>>(DG, bb, it == 4 ? 1 : 0);
    }

    k_row0<<<NBH, 128>>>(outA);
    k_attn<<<dim3(6, NBH), 256>>>(Q, outA);
    k_ctx <<<dim3(7, NBH), 256>>>(outA, outB);
}

// round 17
// speedup vs baseline: 1.7990x; 1.1198x over previous
#include <cuda_runtime.h>

#define SS   384
#define SS1  385
#define NH   8
#define NB   32
#define NBH  256          // NB*NH
#define KD   16
#define EPSF 1e-8f
#define GWEPS 0.05f

typedef unsigned long long ull;

// packed f32x2 FMA (Blackwell): acc = a*b + acc on both lanes
#define FMAX2(acc, a, b) \
    asm("fma.rn.f32x2 %0, %1, %2, %0;" : "+l"(acc) : "l"(a), "l"(b))
#define UNPX2(lo, hi, v) \
    asm("mov.b64 {%0,%1}, %2;" : "=f"(lo), "=f"(hi) : "l"(v))

// ---------------- scratch (static device globals; no allocations) ----------
__device__ float        g_symP[NBH * SS * SS];       // 151 MB
__device__ float        g_deg [NBH * SS];
__device__ unsigned int g_mx  [NBH];
__device__ float        g_a   [NBH * SS];
__device__ float        g_cC1 [NBH * SS];
__device__ float        g_cC2 [NBH * KD];
__device__ float        g_w0  [NBH * KD];
__device__ float        g_csW [NBH * KD];
__device__ float        g_W   [NBH * SS * KD];
__device__ float        g_tens[NBH * SS * KD];
__device__ float        g_Km  [NBH * SS * KD];
__device__ float        g_alpha[NBH];
__device__ float        g_vh  [NBH * SS1 * 32];

// ---------------------------------------------------------------------------
__global__ void k_zero() {
    int t = blockIdx.x * blockDim.x + threadIdx.x;
    if (t < NBH * SS) g_deg[t] = 0.f;
    if (t < NBH)      g_mx[t]  = 0u;
}

// symmetrize P[1:,1:] -> symP, accumulate rowsums (deg) and global max
// grid: (78 tile-pairs, NBH), block: (32,32)
__global__ void k_sym(const float* __restrict__ P) {
    __shared__ float sA[32][33];
    __shared__ float sB[32][33];
    __shared__ float wm[32];

    int bh = blockIdx.y;
    int p  = blockIdx.x;
    int ti = 0;
    while (p >= 12 - ti) { p -= 12 - ti; ti++; }
    int tj = ti + p;

    int x = threadIdx.x, y = threadIdx.y;
    const float* Pb = P + (size_t)bh * SS1 * SS1;
    int r0 = ti * 32, c0 = tj * 32;

    sA[y][x] = Pb[(1 + r0 + y) * SS1 + 1 + c0 + x];
    sB[y][x] = Pb[(1 + c0 + y) * SS1 + 1 + r0 + x];
    __syncthreads();

    float* SPb = g_symP + (size_t)bh * SS * SS;
    float symA = 0.5f * (sA[y][x] + sB[x][y]);
    float symB = 0.5f * (sB[y][x] + sA[x][y]);
    SPb[(r0 + y) * SS + c0 + x] = symA;
    SPb[(c0 + y) * SS + r0 + x] = symB;

    float rs = symA;
    #pragma unroll
    for (int off = 16; off; off >>= 1) rs += __shfl_down_sync(0xffffffffu, rs, off);
    if (x == 0) atomicAdd(&g_deg[bh * SS + r0 + y], rs);
    if (ti != tj) {
        float rs2 = symB;
        #pragma unroll
        for (int off = 16; off; off >>= 1) rs2 += __shfl_down_sync(0xffffffffu, rs2, off);
        if (x == 0) atomicAdd(&g_deg[bh * SS + c0 + y], rs2);
    }

    float m = symA;
    #pragma unroll
    for (int off = 16; off; off >>= 1) m = fmaxf(m, __shfl_down_sync(0xffffffffu, m, off));
    if (x == 0) wm[y] = m;
    __syncthreads();
    if (y == 0) {
        float mm = wm[x];
        #pragma unroll
        for (int off = 16; off; off >>= 1) mm = fmaxf(mm, __shfl_down_sync(0xffffffffu, mm, off));
        if (x == 0) atomicMax(&g_mx[bh], __float_as_uint(mm));
    }
}

// per-bh: a = deg/sum(deg); cC2[l]=sum_k b_k C2[k,l]^2; w0[l]=sum_k b_k C2[l,k];
// csW0 = w0 * sum(a).  grid: NBH, block: 256
__global__ void k_scalars(const float* __restrict__ DG, const float* __restrict__ bb) {
    __shared__ float red[256];
    int bh = blockIdx.x, t = threadIdx.x;

    float s = 0.f;
    for (int i = t; i < SS; i += 256) s += g_deg[bh * SS + i];
    red[t] = s; __syncthreads();
    for (int off = 128; off; off >>= 1) { if (t < off) red[t] += red[t + off]; __syncthreads(); }
    float sumdeg = red[0];
    float inv = 1.f / fmaxf(sumdeg, EPSF);
    float sa  = sumdeg * inv;

    for (int i = t; i < SS; i += 256) g_a[bh * SS + i] = g_deg[bh * SS + i] * inv;

    if (t < KD) {
        int l = t;
        float c2 = 0.f, w0 = 0.f;
        #pragma unroll
        for (int k = 0; k < KD; k++) {
            float bk  = bb[bh * KD + k];
            float ckl = DG[bh * KD * KD + k * KD + l];
            float clk = DG[bh * KD * KD + l * KD + k];
            c2 += bk * ckl * ckl;
            w0 += bk * clk;
        }
        g_cC2[bh * KD + l] = c2;
        g_w0 [bh * KD + l] = w0;
        g_csW[bh * KD + l] = w0 * sa;
    }
}

// fused cc1 + iteration-0 tens/Km (T0 = a (x) b is rank-1)
// grid: (6, NBH), block: 256 (8 warps x 8 rows)
__global__ void k_tens0() {
    __shared__ float4 sa4[96];
    __shared__ float w0s[KD], c2s[KD], css[KD];
    int bh = blockIdx.y, tile = blockIdx.x, t = threadIdx.x;
    if (t < 96) sa4[t] = ((const float4*)(g_a + bh * SS))[t];
    if (t >= 128 && t < 128 + KD) {
        int l = t - 128;
        w0s[l] = g_w0[bh * KD + l];
        c2s[l] = g_cC2[bh * KD + l];
        css[l] = g_csW[bh * KD + l];
    }
    __syncthreads();
    float invm = 1.f / fmaxf(__uint_as_float(g_mx[bh]), EPSF);
    int w = t >> 5, lane = t & 31;
    const float* SPb = g_symP + (size_t)bh * SS * SS;
    const float inve = 1.f / GWEPS;

    for (int rr = 0; rr < 8; rr++) {
        int row = tile * 64 + w * 8 + rr;
        const float4* Pr4 = (const float4*)(SPb + (size_t)row * SS);
        float r1 = 0.f, r2 = 0.f;
        #pragma unroll
        for (int c = 0; c < 3; c++) {
            int m4 = lane + 32 * c;
            float4 p = Pr4[m4];
            float4 a = sa4[m4];
            r1 = fmaf(p.x, a.x, fmaf(p.y, a.y, fmaf(p.z, a.z, fmaf(p.w, a.w, r1))));
            r2 = fmaf(p.x * p.x, a.x, fmaf(p.y * p.y, a.y,
                 fmaf(p.z * p.z, a.z, fmaf(p.w * p.w, a.w, r2))));
        }
        #pragma unroll
        for (int off = 16; off; off >>= 1) {
            r1 += __shfl_xor_sync(0xffffffffu, r1, off);
            r2 += __shfl_xor_sync(0xffffffffu, r2, off);
        }
        float cc1 = 1.f - 2.f * r1 * invm + r2 * invm * invm;
        if (lane == 16) g_cC1[bh * SS + row] = cc1;
        if (lane < KD) {
            float tens = cc1 + c2s[lane] - 2.f * (css[lane] - r1 * w0s[lane] * invm);
            g_Km[(size_t)(bh * SS + row) * KD + lane] = __expf(-tens * inve);
        }
    }
}

// GW tens pass, iterations 1..4: acc = symP @ W with f32x2 pairing over s
// grid: (6, NBH), block: 128
#define WTSTR 394
#define PSTR  66
__global__ void k_tens(int wrTens) {
    __shared__ __align__(16) float sWT[KD * WTSTR];   // transposed W [l][s]
    __shared__ __align__(16) float sP [64 * PSTR];
    int bh = blockIdx.y, tile = blockIdx.x, t = threadIdx.x;
    int lq = t & 3, rg = t >> 2;

    for (int idx = t; idx < SS * KD; idx += 128) {
        int s = idx >> 4, l = idx & 15;
        sWT[l * WTSTR + s] = g_W[(size_t)bh * SS * KD + idx];
    }

    ull acc0[4] = {0,0,0,0}, acc1[4] = {0,0,0,0};
    const float* SPb = g_symP + (size_t)bh * SS * SS + (size_t)(tile * 64) * SS;

    for (int s0 = 0; s0 < SS; s0 += 64) {
        __syncthreads();
        for (int idx = t; idx < 64 * 16; idx += 128) {
            int r = idx >> 4, c4 = idx & 15;
            float4 v = *(const float4*)(SPb + (size_t)r * SS + s0 + c4 * 4);
            float2* d = (float2*)&sP[r * PSTR + c4 * 4];
            d[0] = make_float2(v.x, v.y);
            d[1] = make_float2(v.z, v.w);
        }
        __syncthreads();
        const float* p0r = &sP[(2 * rg) * PSTR];
        const float* p1r = &sP[(2 * rg + 1) * PSTR];
        const float* wb  = &sWT[lq * 4 * WTSTR + s0];
        #pragma unroll 8
        for (int ss = 0; ss < 64; ss += 2) {
            ull pp0 = *(const ull*)(p0r + ss);
            ull pp1 = *(const ull*)(p1r + ss);
            #pragma unroll
            for (int j = 0; j < 4; j++) {
                ull ww = *(const ull*)(wb + j * WTSTR + ss);
                FMAX2(acc0[j], pp0, ww);
                FMAX2(acc1[j], pp1, ww);
            }
        }
    }

    float invm = 1.f / fmaxf(__uint_as_float(g_mx[bh]), EPSF);
    const float inve = 1.f / GWEPS;
    int i = tile * 64 + 2 * rg;
    float cc1a = g_cC1[bh * SS + i];
    float cc1b = g_cC1[bh * SS + i + 1];
    float t0[4], t1[4], k0[4], k1[4];
    #pragma unroll
    for (int j = 0; j < 4; j++) {
        int l = lq * 4 + j;
        float c2 = g_cC2[bh * KD + l];
        float cs = g_csW[bh * KD + l];
        float lo, hi;
        UNPX2(lo, hi, acc0[j]);
        float a0 = lo + hi;
        UNPX2(lo, hi, acc1[j]);
        float a1 = lo + hi;
        t0[j] = cc1a + c2 - 2.f * (cs - a0 * invm);
        t1[j] = cc1b + c2 - 2.f * (cs - a1 * invm);
        k0[j] = __expf(-t0[j] * inve);
        k1[j] = __expf(-t1[j] * inve);
    }
    size_t o0 = (size_t)(bh * SS + i) * KD + lq * 4;
    size_t o1 = o0 + KD;
    *(float4*)(g_Km + o0) = make_float4(k0[0], k0[1], k0[2], k0[3]);
    *(float4*)(g_Km + o1) = make_float4(k1[0], k1[1], k1[2], k1[3]);
    if (wrTens) {
        *(float4*)(g_tens + o0) = make_float4(t0[0], t0[1], t0[2], t0[3]);
        *(float4*)(g_tens + o1) = make_float4(t1[0], t1[1], t1[2], t1[3]);
    }
}

// sinkhorn (20 iters); K-row register-resident; colsums via 256-thread partials
// grid: NBH, block: 384
__global__ void k_sink(const float* __restrict__ DG, const float* __restrict__ bglob, int last) {
    __shared__ __align__(16) float sK[SS * 20];
    __shared__ float su[SS];
    __shared__ __align__(16) float4 sv4[4];
    __shared__ float sb[KD];
    __shared__ float sC2[KD * KD];
    __shared__ float part[16 * KD];
    __shared__ float wpart[12 * KD];
    __shared__ float wsum[12];

    int bh = blockIdx.x, i = threadIdx.x;
    int w = i >> 5, lane = i & 31;

    const float4* Kb = (const float4*)(g_Km + (size_t)bh * SS * KD);
    float4* sK4 = (float4*)sK;
    float4 kv[4];
    #pragma unroll
    for (int q = 0; q < 4; q++) { kv[q] = Kb[i * 4 + q]; sK4[i * 5 + q] = kv[q]; }
    if (i < KD)      { ((float*)sv4)[i] = 1.f; sb[i] = bglob[bh * KD + i]; }
    if (i < KD * KD) sC2[i] = DG[bh * KD * KD + i];
    float a_i = g_a[bh * SS + i];
    __syncthreads();

    float u = 1.f;
    for (int it = 0; it < 20; it++) {
        float4 v0 = sv4[0], v1 = sv4[1], v2 = sv4[2], v3 = sv4[3];
        float s = fmaf(kv[0].x, v0.x, fmaf(kv[0].y, v0.y, fmaf(kv[0].z, v0.z, kv[0].w * v0.w)))
                + fmaf(kv[1].x, v1.x, fmaf(kv[1].y, v1.y, fmaf(kv[1].z, v1.z, kv[1].w * v1.w)))
                + fmaf(kv[2].x, v2.x, fmaf(kv[2].y, v2.y, fmaf(kv[2].z, v2.z, kv[2].w * v2.w)))
                + fmaf(kv[3].x, v3.x, fmaf(kv[3].y, v3.y, fmaf(kv[3].z, v3.z, kv[3].w * v3.w)));
        u = a_i / fmaxf(s, 1e-30f);
        su[i] = u;
        __syncthreads();
        if (i < 256) {
            int k = i & 15, seg = i >> 4;
            const float* col = &sK[(seg * 24) * 20 + k];
            const float* sup = &su[seg * 24];
            float p = 0.f;
            #pragma unroll
            for (int r = 0; r < 24; r++) p = fmaf(col[r * 20], sup[r], p);
            part[seg * KD + k] = p;
        }
        __syncthreads();
        if (i < KD) {
            float sm = 0.f;
            #pragma unroll
            for (int sg = 0; sg < 16; sg++) sm += part[sg * KD + i];
            ((float*)sv4)[i] = sb[i] / fmaxf(sm, 1e-30f);
        }
        __syncthreads();
    }

    float tr[KD];
    #pragma unroll
    for (int q = 0; q < 4; q++) {
        float4 vv = sv4[q];
        tr[4 * q + 0] = u * kv[q].x * vv.x;
        tr[4 * q + 1] = u * kv[q].y * vv.y;
        tr[4 * q + 2] = u * kv[q].z * vv.z;
        tr[4 * q + 3] = u * kv[q].w * vv.w;
    }

    if (!last) {
        float Wr[KD];
        #pragma unroll
        for (int l = 0; l < KD; l++) {
            float s = 0.f;
            #pragma unroll
            for (int k = 0; k < KD; k++) s = fmaf(tr[k], sC2[l * KD + k], s);
            Wr[l] = s;
        }
        float4* Wo = (float4*)(g_W + (size_t)(bh * SS + i) * KD);
        Wo[0] = make_float4(Wr[0],  Wr[1],  Wr[2],  Wr[3]);
        Wo[1] = make_float4(Wr[4],  Wr[5],  Wr[6],  Wr[7]);
        Wo[2] = make_float4(Wr[8],  Wr[9],  Wr[10], Wr[11]);
        Wo[3] = make_float4(Wr[12], Wr[13], Wr[14], Wr[15]);
        #pragma unroll
        for (int k = 0; k < KD; k++)
            #pragma unroll
            for (int off = 16; off; off >>= 1)
                Wr[k] += __shfl_down_sync(0xffffffffu, Wr[k], off);
        if (lane == 0) {
            #pragma unroll
            for (int k = 0; k < KD; k++) wpart[w * KD + k] = Wr[k];
        }
        __syncthreads();
        if (i < KD) {
            float sm = 0.f;
            #pragma unroll
            for (int ww = 0; ww < 12; ww++) sm += wpart[ww * KD + i];
            g_csW[bh * KD + i] = sm;
        }
    } else {
        const float4* tb = (const float4*)(g_tens + (size_t)(bh * SS + i) * KD);
        float g = 0.f;
        #pragma unroll
        for (int q = 0; q < 4; q++) {
            float4 tv = tb[q];
            g = fmaf(tv.x, tr[4*q+0], fmaf(tv.y, tr[4*q+1],
                fmaf(tv.z, tr[4*q+2], fmaf(tv.w, tr[4*q+3], g))));
        }
        #pragma unroll
        for (int off = 16; off; off >>= 1) g += __shfl_down_sync(0xffffffffu, g, off);
        if (lane == 0) wsum[w] = g;
        __syncthreads();
        if (i == 0) {
            float tot = 0.f;
            #pragma unroll
            for (int ww = 0; ww < 12; ww++) tot += wsum[ww];
            g_alpha[bh] = expf(-tot);      // sigma = 1
        }
    }
}

// v projection with k-paired f32x2: vh[b,h,s,d] = sum_k nv[b,s,k]*vw[h*32+d,k] + vb
// grid: (193, 4), block: 256.  64x64 tile, 4x4 per thread, contraction paired.
#define VAST 36
__global__ void k_vproj(const float* __restrict__ nv, const float* __restrict__ vw,
                        const float* __restrict__ vb) {
    __shared__ __align__(16) float sA[64 * VAST];   // [m-row][k], stride 36
    __shared__ __align__(16) float sB[64 * VAST];   // [n-row][k]
    int m0 = blockIdx.x * 64, n0 = blockIdx.y * 64;
    int t = threadIdx.x, tx = t % 16, ty = t / 16;
    ull acc[4][4] = {};

    for (int k0 = 0; k0 < 256; k0 += 32) {
        __syncthreads();
        for (int idx = t; idx < 512; idx += 256) {
            int r = idx >> 3, q = idx & 7;
            int m = m0 + r;
            float4 av = (m < NB * SS1) ? *(const float4*)(nv + (size_t)m * 256 + k0 + q * 4)
                                       : make_float4(0.f, 0.f, 0.f, 0.f);
            *(float4*)&sA[r * VAST + q * 4] = av;
            float4 bv = *(const float4*)(vw + (size_t)(n0 + r) * 256 + k0 + q * 4);
            *(float4*)&sB[r * VAST + q * 4] = bv;
        }
        __syncthreads();
        #pragma unroll
        for (int kk = 0; kk < 32; kk += 4) {
            ulonglong2 av[4], bv[4];
            #pragma unroll
            for (int r = 0; r < 4; r++)
                av[r] = *(const ulonglong2*)&sA[(ty + 16 * r) * VAST + kk];
            #pragma unroll
            for (int c = 0; c < 4; c++)
                bv[c] = *(const ulonglong2*)&sB[(tx + 16 * c) * VAST + kk];
            #pragma unroll
            for (int r = 0; r < 4; r++)
                #pragma unroll
                for (int c = 0; c < 4; c++) {
                    FMAX2(acc[r][c], av[r].x, bv[c].x);
                    FMAX2(acc[r][c], av[r].y, bv[c].y);
                }
        }
    }
    #pragma unroll
    for (int r = 0; r < 4; r++) {
        int m = m0 + ty + 16 * r;
        if (m >= NB * SS1) continue;
        int b = m / SS1, s = m % SS1;
        #pragma unroll
        for (int c = 0; c < 4; c++) {
            int n = n0 + tx + 16 * c;
            int h = n >> 5, d = n & 31;
            float lo, hi;
            UNPX2(lo, hi, acc[r][c]);
            g_vh[((b * NH + h) * SS1 + s) * 32 + d] = lo + hi + vb[n];
        }
    }
}

// attn row 0: [0]=0, [1..384]=1/384
__global__ void k_row0(float* __restrict__ attnOut) {
    int bh = blockIdx.x, t = threadIdx.x;
    float* row = attnOut + (size_t)bh * SS1 * SS1;
    if (t == 0) row[0] = 0.f;
    float v = 1.f / 384.f;
    for (int j = t; j < SS; j += blockDim.x) row[1 + j] = v;
}

// rows 1..384: Q_hat = max(Q,eps)^(1+alpha), diag zeroed, row-normalized
// grid: (6, NBH), block: 256 (8 warps x 8 rows)
__global__ void k_attn(const float* __restrict__ priorQ, float* __restrict__ attnOut) {
    int bh = blockIdx.y, tile = blockIdx.x, t = threadIdx.x;
    int w = t / 32, lane = t % 32;
    float e = 1.f + g_alpha[bh];
    const float* Qb = priorQ + (size_t)bh * SS * SS;
    float* Ab = attnOut + (size_t)bh * SS1 * SS1;

    for (int rr = 0; rr < 8; rr++) {
        int r = tile * 64 + w * 8 + rr;
        const float* qrow = Qb + (size_t)r * SS;
        float tv[12];
        float sum = 0.f;
        #pragma unroll
        for (int c = 0; c < 12; c++) {
            int m = lane + 32 * c;
            float q = fmaxf(qrow[m], EPSF);
            float x = __powf(q, e);
            if (m == r) x = 0.f;
            tv[c] = x;
            sum += x;
        }
        #pragma unroll
        for (int off = 16; off; off >>= 1) sum += __shfl_xor_sync(0xffffffffu, sum, off);
        float inv = 1.f / fmaxf(sum, EPSF);
        float* arow = Ab + (size_t)(r + 1) * SS1;
        if (lane == 0) arow[0] = 0.f;
        #pragma unroll
        for (int c = 0; c < 12; c++) arow[1 + lane + 32 * c] = tv[c] * inv;
    }
}

// context with j-paired f32x2: basis[b,i,h,d] = sum_j attn[bh,i,j] * vh[bh,j,d]
// grid: (7, NBH), block: 256 (tx = d 0..31, ty = row group 0..7)
#define CAST 34
__global__ void k_ctx(const float* __restrict__ attnOut, float* __restrict__ outBasis) {
    __shared__ __align__(8) float sA [64 * CAST];   // [row i][j-pairs]
    __shared__ __align__(8) float sVT[32 * CAST];   // [d][j] transposed
    int bh = blockIdx.y, tile = blockIdx.x, t = threadIdx.x;
    int tx = t & 31, ty = t >> 5;
    ull acc[8] = {};
    const float* Ab = attnOut + (size_t)bh * SS1 * SS1;
    const float* Vb = g_vh + (size_t)bh * SS1 * 32;
    int i0 = tile * 64;

    for (int j0 = 0; j0 < SS1; j0 += 32) {
        __syncthreads();
        for (int idx = t; idx < 64 * 32; idx += 256) {
            int r = idx >> 5, jj = idx & 31;
            int i = i0 + r, j = j0 + jj;
            sA[r * CAST + jj] = (i < SS1 && j < SS1) ? Ab[(size_t)i * SS1 + j] : 0.f;
        }
        for (int idx = t; idx < 32 * 32; idx += 256) {
            int d = idx & 31, jj = idx >> 5;
            int j = j0 + jj;
            sVT[d * CAST + jj] = (j < SS1) ? Vb[(size_t)j * 32 + d] : 0.f;
        }
        __syncthreads();
        #pragma unroll 4
        for (int jj = 0; jj < 32; jj += 2) {
            ull vp = *(const ull*)&sVT[tx * CAST + jj];
            #pragma unroll
            for (int r8 = 0; r8 < 8; r8++) {
                ull ap = *(const ull*)&sA[(ty + 8 * r8) * CAST + jj];
                FMAX2(acc[r8], ap, vp);
            }
        }
    }
    int b = bh >> 3, h = bh & 7;
    #pragma unroll
    for (int r8 = 0; r8 < 8; r8++) {
        int i = i0 + ty + 8 * r8;
        if (i < SS1) {
            float lo, hi;
            UNPX2(lo, hi, acc[r8]);
            outBasis[((size_t)(b * SS1 + i)) * 256 + h * 32 + tx] = lo + hi;
        }
    }
}

// ---------------------------------------------------------------------------
extern "C" void kernel_launch(void* const* d_in, const int* in_sizes, int n_in,
                              void* d_out, int out_size) {
    const float* nv = (const float*)d_in[1];   // name_value_embeddings [32,385,256]
    const float* P  = (const float*)d_in[2];   // shared_attn [32,8,385,385]
    const float* Q  = (const float*)d_in[3];   // prior_Q [32,8,384,384]
    const float* DG = (const float*)d_in[4];   // [32,8,16,16]
    const float* bb = (const float*)d_in[5];   // [32,8,16]
    const float* vw = (const float*)d_in[6];   // [256,256]
    const float* vb = (const float*)d_in[7];   // [256]

    float* outB = (float*)d_out;                                   // basis [32,385,8,32]
    float* outA = (float*)d_out + (out_size - NBH * SS1 * SS1);    // attn  [32,8,385,385]

    k_zero   <<<(NBH * SS + 255) / 256, 256>>>();
    k_sym    <<<dim3(78, NBH), dim3(32, 32)>>>(P);
    k_scalars<<<NBH, 256>>>(DG, bb);
    k_vproj  <<<dim3(193, 4), 256>>>(nv, vw, vb);

    // GW outer iteration 0: fused cc1 + rank-1 tens
    k_tens0<<<dim3(6, NBH), 256>>>();
    k_sink <<<NBH, 384>>>(DG, bb, 0);
    // iterations 1..4
    for (int it = 1; it < 5; it++) {
        k_tens<<<dim3(6, NBH), 128>>>(it == 4 ? 1 : 0);
        k_sink<<<NBH, 384>>>(DG, bb, it == 4 ? 1 : 0);
    }

    k_row0<<<NBH, 128>>>(outA);
    k_attn<<<dim3(6, NBH), 256>>>(Q, outA);
    k_ctx <<<dim3(7, NBH), 256>>>(outA, outB);
}